// round 1
// baseline (speedup 1.0000x reference)
#include <cuda_runtime.h>
#include <math_constants.h>

#define SEQ 2048
#define NTOK 8192           // B*N = 4*2048
#define ATTN_SMEM (((64*132)*2 + 128*68 + 128*132) * 4)

// ---------------- scratch (device globals: no runtime allocation) ----------
__device__ float g_qlat[(size_t)NTOK * 64];
__device__ float g_kvlat[(size_t)NTOK * 64];
__device__ float g_q[(size_t)NTOK * 1024];
__device__ float g_kv[(size_t)NTOK * 2048];
__device__ float g_y[(size_t)NTOK * 1024];

// ---------------------------------------------------------------------------
// gemm_lat: C[8192,64] = rmsnorm( A[8192,1024] @ W[64,1024]^T ) * nw
// block = 64 tokens x 64 outputs, 256 threads, 4x4 register tiles, BK=32
// ---------------------------------------------------------------------------
__global__ __launch_bounds__(256) void gemm_lat_kernel(
    const float* __restrict__ A, const float* __restrict__ W,
    const float* __restrict__ nw, float* __restrict__ C)
{
    __shared__ float As[32][68];   // [k][m]
    __shared__ float Ws[32][68];   // [k][n]
    const int tid = threadIdx.x;
    const int tx = tid & 15, ty = tid >> 4;
    const int m0 = blockIdx.x * 64;

    float acc[4][4] = {};

    for (int k0 = 0; k0 < 1024; k0 += 32) {
        #pragma unroll
        for (int p = 0; p < 2; p++) {
            int f = tid + p * 256;          // 512 float4 per tile
            int r = f >> 3, c4 = f & 7;     // 8 float4 per row of 32
            float4 va = *(const float4*)&A[(size_t)(m0 + r) * 1024 + k0 + c4 * 4];
            As[c4*4+0][r] = va.x; As[c4*4+1][r] = va.y;
            As[c4*4+2][r] = va.z; As[c4*4+3][r] = va.w;
            float4 vb = *(const float4*)&W[(size_t)r * 1024 + k0 + c4 * 4];
            Ws[c4*4+0][r] = vb.x; Ws[c4*4+1][r] = vb.y;
            Ws[c4*4+2][r] = vb.z; Ws[c4*4+3][r] = vb.w;
        }
        __syncthreads();
        #pragma unroll 8
        for (int k = 0; k < 32; k++) {
            float4 a = *(const float4*)&As[k][ty * 4];
            float4 b = *(const float4*)&Ws[k][tx * 4];
            float av[4] = {a.x, a.y, a.z, a.w};
            float bv[4] = {b.x, b.y, b.z, b.w};
            #pragma unroll
            for (int i = 0; i < 4; i++)
                #pragma unroll
                for (int j = 0; j < 4; j++)
                    acc[i][j] += av[i] * bv[j];
        }
        __syncthreads();
    }

    // fused rmsnorm over the 64-wide row (distributed over 16 tx lanes)
    float4 nw4 = *(const float4*)&nw[tx * 4];
    float nwv[4] = {nw4.x, nw4.y, nw4.z, nw4.w};
    #pragma unroll
    for (int i = 0; i < 4; i++) {
        float ss = acc[i][0]*acc[i][0] + acc[i][1]*acc[i][1]
                 + acc[i][2]*acc[i][2] + acc[i][3]*acc[i][3];
        #pragma unroll
        for (int o = 8; o; o >>= 1) ss += __shfl_xor_sync(0xffffffffu, ss, o, 16);
        float sc = rsqrtf(ss * (1.0f / 64.0f) + 1e-6f);
        float4 ov = make_float4(acc[i][0]*sc*nwv[0], acc[i][1]*sc*nwv[1],
                                acc[i][2]*sc*nwv[2], acc[i][3]*sc*nwv[3]);
        *(float4*)&C[(size_t)(m0 + ty * 4 + i) * 64 + tx * 4] = ov;
    }
}

// ---------------------------------------------------------------------------
// gemm128: C[M,N] = A[M,K] @ B[N,K]^T   (row-major, pitch K; C pitch N)
// block tile 128x128, BK=16, 256 threads, 8x8 register tiles
// ---------------------------------------------------------------------------
__global__ __launch_bounds__(256) void gemm128_kernel(
    const float* __restrict__ A, const float* __restrict__ B,
    float* __restrict__ C, int K, int N)
{
    __shared__ float As[16][132];   // [k][m]
    __shared__ float Bs[16][132];   // [k][n]
    const int tid = threadIdx.x;
    const int tx = tid & 15, ty = tid >> 4;
    const int m0 = blockIdx.y * 128, n0 = blockIdx.x * 128;

    float acc[8][8] = {};

    for (int k0 = 0; k0 < K; k0 += 16) {
        #pragma unroll
        for (int p = 0; p < 2; p++) {
            int f = tid + p * 256;          // 512 float4 per tile
            int r = f >> 2, c4 = f & 3;     // 4 float4 per row of 16
            float4 va = *(const float4*)&A[(size_t)(m0 + r) * K + k0 + c4 * 4];
            As[c4*4+0][r] = va.x; As[c4*4+1][r] = va.y;
            As[c4*4+2][r] = va.z; As[c4*4+3][r] = va.w;
            float4 vb = *(const float4*)&B[(size_t)(n0 + r) * K + k0 + c4 * 4];
            Bs[c4*4+0][r] = vb.x; Bs[c4*4+1][r] = vb.y;
            Bs[c4*4+2][r] = vb.z; Bs[c4*4+3][r] = vb.w;
        }
        __syncthreads();
        #pragma unroll 4
        for (int k = 0; k < 16; k++) {
            float av[8], bv[8];
            *(float4*)&av[0] = *(const float4*)&As[k][ty * 8];
            *(float4*)&av[4] = *(const float4*)&As[k][ty * 8 + 4];
            *(float4*)&bv[0] = *(const float4*)&Bs[k][tx * 8];
            *(float4*)&bv[4] = *(const float4*)&Bs[k][tx * 8 + 4];
            #pragma unroll
            for (int i = 0; i < 8; i++)
                #pragma unroll
                for (int j = 0; j < 8; j++)
                    acc[i][j] += av[i] * bv[j];
        }
        __syncthreads();
    }

    #pragma unroll
    for (int i = 0; i < 8; i++) {
        size_t row = (size_t)(m0 + ty * 8 + i) * N + n0;
        #pragma unroll
        for (int j4 = 0; j4 < 8; j4 += 4)
            *(float4*)&C[row + tx * 8 + j4] =
                make_float4(acc[i][j4], acc[i][j4+1], acc[i][j4+2], acc[i][j4+3]);
    }
}

// ---------------------------------------------------------------------------
// Flash attention: per (b,h) and per 128-row Q tile, stream K/V in 128-key
// chunks with online softmax.  q layout [tok][h*64+d] pitch 1024;
// kv layout [tok][h*128 + {k:0..63, v:64..127}] pitch 2048.
// ---------------------------------------------------------------------------
__global__ __launch_bounds__(256, 1) void attn_kernel(
    const float* __restrict__ qf, const float* __restrict__ kvf,
    float* __restrict__ yf)
{
    extern __shared__ float smf[];
    float* Qs = smf;                 // [64][132]  (k-major: [d][token])
    float* Ks = Qs + 64 * 132;       // [64][132]  ([d][key])
    float* Vs = Ks + 64 * 132;       // [128][68]  ([key][d])
    float* Ps = Vs + 128 * 68;       // [128][132] ([qrow][key])

    const int tid = threadIdx.x;
    const int tx = tid & 15, ty = tid >> 4;
    const int bh = blockIdx.y;
    const int b = bh >> 4, h = bh & 15;
    const int q0 = blockIdx.x * 128;

    // load + transpose Q tile, folding in softmax scale D^-0.5 = 0.125
    const float* qbase = qf + ((size_t)b * SEQ + q0) * 1024 + h * 64;
    #pragma unroll
    for (int p = 0; p < 8; p++) {
        int f = tid + p * 256;          // 2048 float4
        int r = f >> 4, c4 = f & 15;    // 16 float4 per 64-wide row
        float4 v = *(const float4*)&qbase[(size_t)r * 1024 + c4 * 4];
        Qs[(c4*4+0)*132 + r] = v.x * 0.125f;
        Qs[(c4*4+1)*132 + r] = v.y * 0.125f;
        Qs[(c4*4+2)*132 + r] = v.z * 0.125f;
        Qs[(c4*4+3)*132 + r] = v.w * 0.125f;
    }

    float acc[8][4] = {};
    float m[8], l[8];
    #pragma unroll
    for (int i = 0; i < 8; i++) { m[i] = -CUDART_INF_F; l[i] = 0.f; }

    for (int kc = 0; kc < SEQ; kc += 128) {
        __syncthreads();   // prev PV done (and Q staged on first iter)
        const float* kbase = kvf + ((size_t)b * SEQ + kc) * 2048 + h * 128;
        #pragma unroll
        for (int p = 0; p < 8; p++) {
            int f = tid + p * 256;
            int r = f >> 4, c4 = f & 15;
            float4 v = *(const float4*)&kbase[(size_t)r * 2048 + c4 * 4];
            Ks[(c4*4+0)*132 + r] = v.x;
            Ks[(c4*4+1)*132 + r] = v.y;
            Ks[(c4*4+2)*132 + r] = v.z;
            Ks[(c4*4+3)*132 + r] = v.w;
            float4 w = *(const float4*)&kbase[(size_t)r * 2048 + 64 + c4 * 4];
            *(float4*)&Vs[r * 68 + c4 * 4] = w;
        }
        __syncthreads();

        // S[128,128] = (Q*scale) @ K^T : 8x8 per thread
        float s[8][8] = {};
        #pragma unroll 4
        for (int k = 0; k < 64; k++) {
            float av[8], bv[8];
            *(float4*)&av[0] = *(const float4*)&Qs[k * 132 + ty * 8];
            *(float4*)&av[4] = *(const float4*)&Qs[k * 132 + ty * 8 + 4];
            *(float4*)&bv[0] = *(const float4*)&Ks[k * 132 + tx * 8];
            *(float4*)&bv[4] = *(const float4*)&Ks[k * 132 + tx * 8 + 4];
            #pragma unroll
            for (int i = 0; i < 8; i++)
                #pragma unroll
                for (int j = 0; j < 8; j++)
                    s[i][j] += av[i] * bv[j];
        }

        // online softmax per row (row group = 16 tx lanes)
        #pragma unroll
        for (int i = 0; i < 8; i++) {
            float mx = s[i][0];
            #pragma unroll
            for (int j = 1; j < 8; j++) mx = fmaxf(mx, s[i][j]);
            #pragma unroll
            for (int o = 8; o; o >>= 1)
                mx = fmaxf(mx, __shfl_xor_sync(0xffffffffu, mx, o, 16));
            float mn = fmaxf(m[i], mx);
            float corr = __expf(m[i] - mn);
            m[i] = mn;
            float rs = 0.f;
            #pragma unroll
            for (int j = 0; j < 8; j++) {
                float p = __expf(s[i][j] - mn);
                s[i][j] = p; rs += p;
            }
            #pragma unroll
            for (int o = 8; o; o >>= 1)
                rs += __shfl_xor_sync(0xffffffffu, rs, o, 16);
            l[i] = l[i] * corr + rs;
            #pragma unroll
            for (int j = 0; j < 4; j++) acc[i][j] *= corr;
            *(float4*)&Ps[(ty*8+i)*132 + tx*8]     = make_float4(s[i][0], s[i][1], s[i][2], s[i][3]);
            *(float4*)&Ps[(ty*8+i)*132 + tx*8 + 4] = make_float4(s[i][4], s[i][5], s[i][6], s[i][7]);
        }
        __syncthreads();

        // O += P @ V : 8 rows x 4 d-cols per thread, k unrolled by 4
        #pragma unroll 2
        for (int k = 0; k < 128; k += 4) {
            float4 v0 = *(const float4*)&Vs[(k+0)*68 + tx*4];
            float4 v1 = *(const float4*)&Vs[(k+1)*68 + tx*4];
            float4 v2 = *(const float4*)&Vs[(k+2)*68 + tx*4];
            float4 v3 = *(const float4*)&Vs[(k+3)*68 + tx*4];
            #pragma unroll
            for (int i = 0; i < 8; i++) {
                float4 pp = *(const float4*)&Ps[(ty*8+i)*132 + k];
                acc[i][0] += pp.x*v0.x + pp.y*v1.x + pp.z*v2.x + pp.w*v3.x;
                acc[i][1] += pp.x*v0.y + pp.y*v1.y + pp.z*v2.y + pp.w*v3.y;
                acc[i][2] += pp.x*v0.z + pp.y*v1.z + pp.z*v2.z + pp.w*v3.z;
                acc[i][3] += pp.x*v0.w + pp.y*v1.w + pp.z*v2.w + pp.w*v3.w;
            }
        }
    }

    // normalize and store y[tok][h*64+d]
    float* ybase = yf + ((size_t)b * SEQ + q0) * 1024 + h * 64;
    #pragma unroll
    for (int i = 0; i < 8; i++) {
        float inv = 1.0f / l[i];
        *(float4*)&ybase[(size_t)(ty*8+i) * 1024 + tx*4] =
            make_float4(acc[i][0]*inv, acc[i][1]*inv, acc[i][2]*inv, acc[i][3]*inv);
    }
}

// ---------------------------------------------------------------------------
extern "C" void kernel_launch(void* const* d_in, const int* in_sizes, int n_in,
                              void* d_out, int out_size)
{
    const float* x      = (const float*)d_in[0];
    const float* w_kv_a = (const float*)d_in[1];
    const float* w_kv_b = (const float*)d_in[2];
    const float* w_q_a  = (const float*)d_in[3];
    const float* w_q_b  = (const float*)d_in[4];
    const float* w_proj = (const float*)d_in[5];
    const float* kv_nw  = (const float*)d_in[6];
    const float* q_nw   = (const float*)d_in[7];
    float* out = (float*)d_out;

    float *qlat, *kvlat, *q, *kv, *y;
    cudaGetSymbolAddress((void**)&qlat,  g_qlat);
    cudaGetSymbolAddress((void**)&kvlat, g_kvlat);
    cudaGetSymbolAddress((void**)&q,     g_q);
    cudaGetSymbolAddress((void**)&kv,    g_kv);
    cudaGetSymbolAddress((void**)&y,     g_y);

    cudaFuncSetAttribute(attn_kernel,
                         cudaFuncAttributeMaxDynamicSharedMemorySize, ATTN_SMEM);

    // latent projections + rmsnorm
    gemm_lat_kernel<<<128, 256>>>(x, w_q_a,  q_nw,  qlat);
    gemm_lat_kernel<<<128, 256>>>(x, w_kv_a, kv_nw, kvlat);

    // up-projections
    gemm128_kernel<<<dim3(8, 64),  256>>>(qlat,  w_q_b,  q,  64, 1024);
    gemm128_kernel<<<dim3(16, 64), 256>>>(kvlat, w_kv_b, kv, 64, 2048);

    // attention
    attn_kernel<<<dim3(16, 64), 256, ATTN_SMEM>>>(q, kv, y);

    // output projection
    gemm128_kernel<<<dim3(8, 64), 256>>>(y, w_proj, out, 1024, 1024);
}

// round 3
// speedup vs baseline: 2.0089x; 2.0089x over previous
#include <cuda_runtime.h>
#include <cuda_bf16.h>
#include <cstdint>

#define SEQ   2048
#define NTOK  8192

// ---------------- scratch (device globals: no runtime allocation) ----------
__device__ float g_qlat [(size_t)NTOK * 64];
__device__ float g_kvlat[(size_t)NTOK * 64];
__device__ float g_q  [(size_t)NTOK * 1024];
__device__ float g_kv [(size_t)NTOK * 2048];
__device__ float g_y  [(size_t)NTOK * 1024];

// ---------------- helpers ---------------------------------------------------
static __device__ __forceinline__ uint32_t bfpack(float lo, float hi) {
    uint32_t r;
    asm("cvt.rn.bf16x2.f32 %0, %1, %2;" : "=r"(r) : "f"(hi), "f"(lo));
    return r;
}
// split (x,y) into bf16x2 hi pair + bf16x2 lo-residual pair
static __device__ __forceinline__ void split2(float x, float y,
                                              uint32_t& h, uint32_t& l) {
    h = bfpack(x, y);
    __nv_bfloat162 hb = *reinterpret_cast<__nv_bfloat162*>(&h);
    l = bfpack(x - __bfloat162float(hb.x), y - __bfloat162float(hb.y));
}

// D += A(16x16 bf16, row) * B(16x8 bf16, col)
#define MMAB(c, a0, a1, a2, a3, b0, b1)                                        \
    asm volatile("mma.sync.aligned.m16n8k16.row.col.f32.bf16.bf16.f32 "        \
        "{%0,%1,%2,%3},{%4,%5,%6,%7},{%8,%9},{%0,%1,%2,%3};"                   \
        : "+f"((c)[0]), "+f"((c)[1]), "+f"((c)[2]), "+f"((c)[3])               \
        : "r"(a0), "r"(a1), "r"(a2), "r"(a3), "r"(b0), "r"(b1))

// 3-term split product: ah*bh + ah*bl + al*bh
#define MMAX3(c, ah, al, bh0, bh1, bl0, bl1) do {                              \
    MMAB(c, (ah)[0], (ah)[1], (ah)[2], (ah)[3], bh0, bh1);                     \
    MMAB(c, (ah)[0], (ah)[1], (ah)[2], (ah)[3], bl0, bl1);                     \
    MMAB(c, (al)[0], (al)[1], (al)[2], (al)[3], bh0, bh1);                     \
} while (0)

// ======================================================================
// gemm_tc: C[M,N] = A[M,K] @ B[N,K]^T   bf16x3 mma.sync, tile 128x128, BK=16
// rows: hi halves at words [0..7], lo at words [8..15], pitch 20 words
// ======================================================================
__global__ __launch_bounds__(256) void gemm_tc(
    const float* __restrict__ A, const float* __restrict__ B,
    float* __restrict__ C, int K, int N)
{
    __shared__ uint32_t AsW[128 * 20];
    __shared__ uint32_t BsW[128 * 20];
    const int tid = threadIdx.x;
    const int w = tid >> 5, lane = tid & 31;
    const int g = lane >> 2, tig = lane & 3;
    const int wm = w & 1, wn = w >> 1;            // warp tile 64(M) x 32(N)
    const int m0 = blockIdx.y * 128, n0 = blockIdx.x * 128;

    float c[4][4][4] = {};

    for (int k0 = 0; k0 < K; k0 += 16) {
        #pragma unroll
        for (int p = 0; p < 2; p++) {
            int f = tid + p * 256, r = f >> 2, c4 = f & 3;
            float4 va = *(const float4*)&A[(size_t)(m0 + r) * K + k0 + c4 * 4];
            uint32_t h0, h1, l0, l1;
            split2(va.x, va.y, h0, l0); split2(va.z, va.w, h1, l1);
            AsW[r * 20 + 2 * c4] = h0;      AsW[r * 20 + 2 * c4 + 1] = h1;
            AsW[r * 20 + 8 + 2 * c4] = l0;  AsW[r * 20 + 9 + 2 * c4] = l1;
            float4 vb = *(const float4*)&B[(size_t)(n0 + r) * K + k0 + c4 * 4];
            split2(vb.x, vb.y, h0, l0); split2(vb.z, vb.w, h1, l1);
            BsW[r * 20 + 2 * c4] = h0;      BsW[r * 20 + 2 * c4 + 1] = h1;
            BsW[r * 20 + 8 + 2 * c4] = l0;  BsW[r * 20 + 9 + 2 * c4] = l1;
        }
        __syncthreads();

        uint32_t ah[4][4], al[4][4], bh[4][2], bl[4][2];
        #pragma unroll
        for (int mt = 0; mt < 4; mt++) {
            int r = wm * 64 + mt * 16 + g;
            ah[mt][0] = AsW[r * 20 + tig];            ah[mt][1] = AsW[(r + 8) * 20 + tig];
            ah[mt][2] = AsW[r * 20 + 4 + tig];        ah[mt][3] = AsW[(r + 8) * 20 + 4 + tig];
            al[mt][0] = AsW[r * 20 + 8 + tig];        al[mt][1] = AsW[(r + 8) * 20 + 8 + tig];
            al[mt][2] = AsW[r * 20 + 12 + tig];       al[mt][3] = AsW[(r + 8) * 20 + 12 + tig];
        }
        #pragma unroll
        for (int nt = 0; nt < 4; nt++) {
            int rn = wn * 32 + nt * 8 + g;
            bh[nt][0] = BsW[rn * 20 + tig];           bh[nt][1] = BsW[rn * 20 + 4 + tig];
            bl[nt][0] = BsW[rn * 20 + 8 + tig];       bl[nt][1] = BsW[rn * 20 + 12 + tig];
        }
        #pragma unroll
        for (int mt = 0; mt < 4; mt++)
            #pragma unroll
            for (int nt = 0; nt < 4; nt++)
                MMAX3(c[mt][nt], ah[mt], al[mt], bh[nt][0], bh[nt][1], bl[nt][0], bl[nt][1]);
        __syncthreads();
    }

    #pragma unroll
    for (int mt = 0; mt < 4; mt++)
        #pragma unroll
        for (int nt = 0; nt < 4; nt++) {
            int r0 = m0 + wm * 64 + mt * 16 + g;
            int col = n0 + wn * 32 + nt * 8 + 2 * tig;
            *(float2*)&C[(size_t)r0 * N + col]       = make_float2(c[mt][nt][0], c[mt][nt][1]);
            *(float2*)&C[(size_t)(r0 + 8) * N + col] = make_float2(c[mt][nt][2], c[mt][nt][3]);
        }
}

// ======================================================================
// gemm_lat: C[8192,64] = rmsnorm(A[8192,1024] @ W[64,1024]^T) * nw
// tile 128x64, warp tile 32x32
// ======================================================================
__global__ __launch_bounds__(256) void gemm_lat(
    const float* __restrict__ A, const float* __restrict__ W,
    const float* __restrict__ nw, float* __restrict__ C)
{
    __shared__ uint32_t AsW[128 * 20];
    __shared__ uint32_t BsW[64 * 20];
    __shared__ float Cb[128][65];
    __shared__ float nws[64];
    const int tid = threadIdx.x;
    const int w = tid >> 5, lane = tid & 31;
    const int g = lane >> 2, tig = lane & 3;
    const int wm = w >> 1, wn = w & 1;            // warp tile 32(M) x 32(N)
    const int m0 = blockIdx.x * 128;

    if (tid < 64) nws[tid] = nw[tid];

    float c[2][4][4] = {};

    for (int k0 = 0; k0 < 1024; k0 += 16) {
        #pragma unroll
        for (int p = 0; p < 2; p++) {
            int f = tid + p * 256, r = f >> 2, c4 = f & 3;
            float4 va = *(const float4*)&A[(size_t)(m0 + r) * 1024 + k0 + c4 * 4];
            uint32_t h0, h1, l0, l1;
            split2(va.x, va.y, h0, l0); split2(va.z, va.w, h1, l1);
            AsW[r * 20 + 2 * c4] = h0;      AsW[r * 20 + 2 * c4 + 1] = h1;
            AsW[r * 20 + 8 + 2 * c4] = l0;  AsW[r * 20 + 9 + 2 * c4] = l1;
        }
        {
            int r = tid >> 2, c4 = tid & 3;
            float4 vb = *(const float4*)&W[(size_t)r * 1024 + k0 + c4 * 4];
            uint32_t h0, h1, l0, l1;
            split2(vb.x, vb.y, h0, l0); split2(vb.z, vb.w, h1, l1);
            BsW[r * 20 + 2 * c4] = h0;      BsW[r * 20 + 2 * c4 + 1] = h1;
            BsW[r * 20 + 8 + 2 * c4] = l0;  BsW[r * 20 + 9 + 2 * c4] = l1;
        }
        __syncthreads();

        uint32_t ah[2][4], al[2][4], bh[4][2], bl[4][2];
        #pragma unroll
        for (int mt = 0; mt < 2; mt++) {
            int r = wm * 32 + mt * 16 + g;
            ah[mt][0] = AsW[r * 20 + tig];            ah[mt][1] = AsW[(r + 8) * 20 + tig];
            ah[mt][2] = AsW[r * 20 + 4 + tig];        ah[mt][3] = AsW[(r + 8) * 20 + 4 + tig];
            al[mt][0] = AsW[r * 20 + 8 + tig];        al[mt][1] = AsW[(r + 8) * 20 + 8 + tig];
            al[mt][2] = AsW[r * 20 + 12 + tig];       al[mt][3] = AsW[(r + 8) * 20 + 12 + tig];
        }
        #pragma unroll
        for (int nt = 0; nt < 4; nt++) {
            int rn = wn * 32 + nt * 8 + g;
            bh[nt][0] = BsW[rn * 20 + tig];           bh[nt][1] = BsW[rn * 20 + 4 + tig];
            bl[nt][0] = BsW[rn * 20 + 8 + tig];       bl[nt][1] = BsW[rn * 20 + 12 + tig];
        }
        #pragma unroll
        for (int mt = 0; mt < 2; mt++)
            #pragma unroll
            for (int nt = 0; nt < 4; nt++)
                MMAX3(c[mt][nt], ah[mt], al[mt], bh[nt][0], bh[nt][1], bl[nt][0], bl[nt][1]);
        __syncthreads();
    }

    #pragma unroll
    for (int mt = 0; mt < 2; mt++)
        #pragma unroll
        for (int nt = 0; nt < 4; nt++) {
            int rr = wm * 32 + mt * 16 + g, col = wn * 32 + nt * 8 + 2 * tig;
            Cb[rr][col]     = c[mt][nt][0];  Cb[rr][col + 1]     = c[mt][nt][1];
            Cb[rr + 8][col] = c[mt][nt][2];  Cb[rr + 8][col + 1] = c[mt][nt][3];
        }
    __syncthreads();

    if (tid < 128) {
        float v[64], ss = 0.f;
        #pragma unroll
        for (int j = 0; j < 64; j++) { v[j] = Cb[tid][j]; ss += v[j] * v[j]; }
        float sc = rsqrtf(ss * (1.0f / 64.0f) + 1e-6f);
        float* dst = &C[(size_t)(m0 + tid) * 64];
        #pragma unroll
        for (int j = 0; j < 64; j += 4)
            *(float4*)&dst[j] = make_float4(v[j] * sc * nws[j],   v[j+1] * sc * nws[j+1],
                                            v[j+2] * sc * nws[j+2], v[j+3] * sc * nws[j+3]);
    }
}

// ======================================================================
// attn_tc: flash attention, bf16x3 mma.sync. 128 q-rows/CTA, 128-key chunks.
// No online max (logits sigma~1). Warp w owns q-rows [16w,16w+16).
// smem words: QsW 128x72 | KsW 128x72 | VbfW 64x132 | PsW 128x136 (fp32 V tmp overlaid)
// ======================================================================
#define ATTN_SMEM 177152

__global__ __launch_bounds__(256, 1) void attn_tc(
    const float* __restrict__ qf, const float* __restrict__ kvf,
    float* __restrict__ yf)
{
    extern __shared__ uint32_t smw[];
    uint32_t* QsW  = smw;                   // 128*72 = 9216
    uint32_t* KsW  = QsW + 9216;            // 9216
    uint32_t* VbfW = KsW + 9216;            // 64*132 = 8448
    uint32_t* PsW  = VbfW + 8448;           // 128*136 = 17408
    float*    Vtmp = (float*)PsW;           // overlay: 128*68 fp32

    const int tid = threadIdx.x;
    const int w = tid >> 5, lane = tid & 31;
    const int g = lane >> 2, tig = lane & 3;
    const int r0 = w * 16 + g;              // q-row (and +8)
    const int bh = blockIdx.y, b = bh >> 4, h = bh & 15;
    const int q0 = blockIdx.x * 128;

    // stage Q once (scaled by D^-0.5 = 0.125), hi|lo packed rows
    const float* qb = qf + ((size_t)b * SEQ + q0) * 1024 + h * 64;
    #pragma unroll
    for (int p = 0; p < 8; p++) {
        int f = tid + p * 256, r = f >> 4, c4 = f & 15;
        float4 v = *(const float4*)&qb[(size_t)r * 1024 + c4 * 4];
        uint32_t h0, h1, l0, l1;
        split2(v.x * 0.125f, v.y * 0.125f, h0, l0);
        split2(v.z * 0.125f, v.w * 0.125f, h1, l1);
        QsW[r * 72 + 2 * c4] = h0;       QsW[r * 72 + 2 * c4 + 1] = h1;
        QsW[r * 72 + 32 + 2 * c4] = l0;  QsW[r * 72 + 33 + 2 * c4] = l1;
    }

    float o[8][4] = {};
    float lsum0 = 0.f, lsum1 = 0.f;

    for (int kc = 0; kc < 16; kc++) {
        __syncthreads();   // prev PV done; Q staged (kc=0)

        // stage K (bf16 hi/lo) and V (fp32 tmp)
        const float* kb = kvf + ((size_t)b * SEQ + kc * 128) * 2048 + h * 128;
        #pragma unroll
        for (int p = 0; p < 8; p++) {
            int f = tid + p * 256, key = f >> 4, c4 = f & 15;
            float4 v = *(const float4*)&kb[(size_t)key * 2048 + c4 * 4];
            uint32_t h0, h1, l0, l1;
            split2(v.x, v.y, h0, l0); split2(v.z, v.w, h1, l1);
            KsW[key * 72 + 2 * c4] = h0;       KsW[key * 72 + 2 * c4 + 1] = h1;
            KsW[key * 72 + 32 + 2 * c4] = l0;  KsW[key * 72 + 33 + 2 * c4] = l1;
            float4 vv = *(const float4*)&kb[(size_t)key * 2048 + 64 + c4 * 4];
            *(float4*)&Vtmp[key * 68 + c4 * 4] = vv;
        }
        __syncthreads();

        // transpose V: [key][d] fp32 -> [d][key-pair] bf16 hi/lo
        #pragma unroll
        for (int p = 0; p < 4; p++) {
            int idx = tid + p * 256;
            int kp = (idx & 7) | ((idx >> 7) << 3);   // key pair 0..63
            int c4 = (idx >> 3) & 15;                 // d group 0..15
            float4 v0 = *(const float4*)&Vtmp[(2 * kp) * 68 + c4 * 4];
            float4 v1 = *(const float4*)&Vtmp[(2 * kp + 1) * 68 + c4 * 4];
            uint32_t hh, ll;
            split2(v0.x, v1.x, hh, ll);
            VbfW[(4*c4+0) * 132 + kp] = hh;  VbfW[(4*c4+0) * 132 + 64 + kp] = ll;
            split2(v0.y, v1.y, hh, ll);
            VbfW[(4*c4+1) * 132 + kp] = hh;  VbfW[(4*c4+1) * 132 + 64 + kp] = ll;
            split2(v0.z, v1.z, hh, ll);
            VbfW[(4*c4+2) * 132 + kp] = hh;  VbfW[(4*c4+2) * 132 + 64 + kp] = ll;
            split2(v0.w, v1.w, hh, ll);
            VbfW[(4*c4+3) * 132 + kp] = hh;  VbfW[(4*c4+3) * 132 + 64 + kp] = ll;
        }

        // S = Q @ K^T  (k-dim d=64 -> 4 k16 steps)
        float s[16][4] = {};
        #pragma unroll
        for (int ks = 0; ks < 4; ks++) {
            uint32_t qh[4], ql[4];
            qh[0] = QsW[r0 * 72 + 8 * ks + tig];            qh[1] = QsW[(r0 + 8) * 72 + 8 * ks + tig];
            qh[2] = QsW[r0 * 72 + 8 * ks + 4 + tig];        qh[3] = QsW[(r0 + 8) * 72 + 8 * ks + 4 + tig];
            ql[0] = QsW[r0 * 72 + 32 + 8 * ks + tig];       ql[1] = QsW[(r0 + 8) * 72 + 32 + 8 * ks + tig];
            ql[2] = QsW[r0 * 72 + 36 + 8 * ks + tig];       ql[3] = QsW[(r0 + 8) * 72 + 36 + 8 * ks + tig];
            #pragma unroll
            for (int nt = 0; nt < 16; nt++) {
                int rn = nt * 8 + g;
                uint32_t kh0 = KsW[rn * 72 + 8 * ks + tig];
                uint32_t kh1 = KsW[rn * 72 + 8 * ks + 4 + tig];
                uint32_t kl0 = KsW[rn * 72 + 32 + 8 * ks + tig];
                uint32_t kl1 = KsW[rn * 72 + 36 + 8 * ks + tig];
                MMAX3(s[nt], qh, ql, kh0, kh1, kl0, kl1);
            }
        }
        __syncthreads();   // transposes done before P overwrites Vtmp region

        // p = exp(s); accumulate row sums; stage P (bf16 hi/lo)
        #pragma unroll
        for (int nt = 0; nt < 16; nt++) {
            float e0 = __expf(s[nt][0]), e1 = __expf(s[nt][1]);
            float e2 = __expf(s[nt][2]), e3 = __expf(s[nt][3]);
            lsum0 += e0 + e1; lsum1 += e2 + e3;
            uint32_t hh, ll;
            split2(e0, e1, hh, ll);
            PsW[r0 * 136 + 4 * nt + tig] = hh;        PsW[r0 * 136 + 64 + 4 * nt + tig] = ll;
            split2(e2, e3, hh, ll);
            PsW[(r0 + 8) * 136 + 4 * nt + tig] = hh;  PsW[(r0 + 8) * 136 + 64 + 4 * nt + tig] = ll;
        }
        __syncwarp();

        // O += P @ V  (k-dim key=128 -> 8 k16 steps)
        #pragma unroll
        for (int ks = 0; ks < 8; ks++) {
            uint32_t ph[4], pl[4];
            ph[0] = PsW[r0 * 136 + 8 * ks + tig];           ph[1] = PsW[(r0 + 8) * 136 + 8 * ks + tig];
            ph[2] = PsW[r0 * 136 + 8 * ks + 4 + tig];       ph[3] = PsW[(r0 + 8) * 136 + 8 * ks + 4 + tig];
            pl[0] = PsW[r0 * 136 + 64 + 8 * ks + tig];      pl[1] = PsW[(r0 + 8) * 136 + 64 + 8 * ks + tig];
            pl[2] = PsW[r0 * 136 + 68 + 8 * ks + tig];      pl[3] = PsW[(r0 + 8) * 136 + 68 + 8 * ks + tig];
            #pragma unroll
            for (int nt = 0; nt < 8; nt++) {
                int d = nt * 8 + g;
                uint32_t vh0 = VbfW[d * 132 + 8 * ks + tig];
                uint32_t vh1 = VbfW[d * 132 + 8 * ks + 4 + tig];
                uint32_t vl0 = VbfW[d * 132 + 64 + 8 * ks + tig];
                uint32_t vl1 = VbfW[d * 132 + 68 + 8 * ks + tig];
                MMAX3(o[nt], ph, pl, vh0, vh1, vl0, vl1);
            }
        }
    }

    // reduce l over the 4 tig lanes (rows r0, r0+8)
    lsum0 += __shfl_xor_sync(0xffffffffu, lsum0, 1);
    lsum0 += __shfl_xor_sync(0xffffffffu, lsum0, 2);
    lsum1 += __shfl_xor_sync(0xffffffffu, lsum1, 1);
    lsum1 += __shfl_xor_sync(0xffffffffu, lsum1, 2);
    float inv0 = 1.0f / lsum0, inv1 = 1.0f / lsum1;

    float* y0 = yf + ((size_t)b * SEQ + q0 + r0) * 1024 + h * 64;
    float* y1 = yf + ((size_t)b * SEQ + q0 + r0 + 8) * 1024 + h * 64;
    #pragma unroll
    for (int nt = 0; nt < 8; nt++) {
        int col = nt * 8 + 2 * tig;
        *(float2*)&y0[col] = make_float2(o[nt][0] * inv0, o[nt][1] * inv0);
        *(float2*)&y1[col] = make_float2(o[nt][2] * inv1, o[nt][3] * inv1);
    }
}

// ---------------------------------------------------------------------------
extern "C" void kernel_launch(void* const* d_in, const int* in_sizes, int n_in,
                              void* d_out, int out_size)
{
    const float* x      = (const float*)d_in[0];
    const float* w_kv_a = (const float*)d_in[1];
    const float* w_kv_b = (const float*)d_in[2];
    const float* w_q_a  = (const float*)d_in[3];
    const float* w_q_b  = (const float*)d_in[4];
    const float* w_proj = (const float*)d_in[5];
    const float* kv_nw  = (const float*)d_in[6];
    const float* q_nw   = (const float*)d_in[7];
    float* out = (float*)d_out;

    float *qlat, *kvlat, *q, *kv, *y;
    cudaGetSymbolAddress((void**)&qlat,  g_qlat);
    cudaGetSymbolAddress((void**)&kvlat, g_kvlat);
    cudaGetSymbolAddress((void**)&q,     g_q);
    cudaGetSymbolAddress((void**)&kv,    g_kv);
    cudaGetSymbolAddress((void**)&y,     g_y);

    cudaFuncSetAttribute(attn_tc,
                         cudaFuncAttributeMaxDynamicSharedMemorySize, ATTN_SMEM);

    // latent projections + fused rmsnorm
    gemm_lat<<<64, 256>>>(x, w_q_a,  q_nw,  qlat);
    gemm_lat<<<64, 256>>>(x, w_kv_a, kv_nw, kvlat);

    // up-projections (K=64)
    gemm_tc<<<dim3(8, 64),  256>>>(qlat,  w_q_b,  q,  64, 1024);
    gemm_tc<<<dim3(16, 64), 256>>>(kvlat, w_kv_b, kv, 64, 2048);

    // attention
    attn_tc<<<dim3(16, 64), 256, ATTN_SMEM>>>(q, kv, y);

    // output projection
    gemm_tc<<<dim3(8, 64), 256>>>(y, w_proj, out, 1024, 1024);
}

// round 4
// speedup vs baseline: 2.6869x; 1.3375x over previous
#include <cuda_runtime.h>
#include <cuda_bf16.h>
#include <cstdint>

#define SEQ   2048
#define NTOK  8192

// ---------------- scratch (device globals: no runtime allocation) ----------
__device__ float g_qlat [(size_t)NTOK * 64];
__device__ float g_kvlat[(size_t)NTOK * 64];
__device__ float g_y  [(size_t)NTOK * 1024];
// bf16 hi/lo split tensors, per-head layout [(b*16+h)][seq][64]
__device__ __nv_bfloat16 g_qh[(size_t)NTOK * 1024];
__device__ __nv_bfloat16 g_ql[(size_t)NTOK * 1024];
__device__ __nv_bfloat16 g_kh[(size_t)NTOK * 1024];
__device__ __nv_bfloat16 g_kl[(size_t)NTOK * 1024];
__device__ __nv_bfloat16 g_vh[(size_t)NTOK * 1024];
__device__ __nv_bfloat16 g_vl[(size_t)NTOK * 1024];

// ---------------- helpers ---------------------------------------------------
static __device__ __forceinline__ uint32_t smem_u32(const void* p) {
    uint32_t a;
    asm("{ .reg .u64 t; cvta.to.shared.u64 t, %1; cvt.u32.u64 %0, t; }"
        : "=r"(a) : "l"(p));
    return a;
}
static __device__ __forceinline__ uint32_t bfpack(float lo, float hi) {
    uint32_t r;
    asm("cvt.rn.bf16x2.f32 %0, %1, %2;" : "=r"(r) : "f"(hi), "f"(lo));
    return r;
}
static __device__ __forceinline__ void split2(float x, float y,
                                              uint32_t& h, uint32_t& l) {
    h = bfpack(x, y);
    __nv_bfloat162 hb = *reinterpret_cast<__nv_bfloat162*>(&h);
    l = bfpack(x - __bfloat162float(hb.x), y - __bfloat162float(hb.y));
}
// swizzled smem addr: 128B rows of 8 x 16B chunks, chunk ^= row&7
static __device__ __forceinline__ uint32_t lda(uint32_t base, int row, int ch) {
    return base + row * 128 + (((uint32_t)ch ^ ((uint32_t)row & 7u)) << 4);
}

#define MMAB(c, a0, a1, a2, a3, b0, b1)                                        \
    asm volatile("mma.sync.aligned.m16n8k16.row.col.f32.bf16.bf16.f32 "        \
        "{%0,%1,%2,%3},{%4,%5,%6,%7},{%8,%9},{%0,%1,%2,%3};"                   \
        : "+f"((c)[0]), "+f"((c)[1]), "+f"((c)[2]), "+f"((c)[3])               \
        : "r"(a0), "r"(a1), "r"(a2), "r"(a3), "r"(b0), "r"(b1))

#define MMAX3(c, ah, al, bh0, bh1, bl0, bl1) do {                              \
    MMAB(c, (ah)[0], (ah)[1], (ah)[2], (ah)[3], bh0, bh1);                     \
    MMAB(c, (ah)[0], (ah)[1], (ah)[2], (ah)[3], bl0, bl1);                     \
    MMAB(c, (al)[0], (al)[1], (al)[2], (al)[3], bh0, bh1);                     \
} while (0)

#define LDSM4(r, addr)                                                         \
    asm volatile("ldmatrix.sync.aligned.m8n8.x4.shared.b16 {%0,%1,%2,%3}, [%4];" \
        : "=r"((r)[0]), "=r"((r)[1]), "=r"((r)[2]), "=r"((r)[3]) : "r"(addr))
#define LDSM4T(r, addr)                                                        \
    asm volatile("ldmatrix.sync.aligned.m8n8.x4.trans.shared.b16 {%0,%1,%2,%3}, [%4];" \
        : "=r"((r)[0]), "=r"((r)[1]), "=r"((r)[2]), "=r"((r)[3]) : "r"(addr))
#define CPA16(dst, src)                                                        \
    asm volatile("cp.async.cg.shared.global [%0], [%1], 16;" :: "r"(dst), "l"(src))
#define CPCOMMIT() asm volatile("cp.async.commit_group;" ::: "memory")
#define CPWAIT(n)  asm volatile("cp.async.wait_group %0;" :: "n"(n) : "memory")

// ======================================================================
// gemm_tc: C[M,N] = A[M,K] @ B[N,K]^T   bf16x3 mma.sync (fp32 out)
// ======================================================================
__global__ __launch_bounds__(256) void gemm_tc(
    const float* __restrict__ A, const float* __restrict__ B,
    float* __restrict__ C, int K, int N)
{
    __shared__ uint32_t AsW[128 * 20];
    __shared__ uint32_t BsW[128 * 20];
    const int tid = threadIdx.x;
    const int w = tid >> 5, lane = tid & 31;
    const int g = lane >> 2, tig = lane & 3;
    const int wm = w & 1, wn = w >> 1;
    const int m0 = blockIdx.y * 128, n0 = blockIdx.x * 128;

    float c[4][4][4] = {};

    for (int k0 = 0; k0 < K; k0 += 16) {
        #pragma unroll
        for (int p = 0; p < 2; p++) {
            int f = tid + p * 256, r = f >> 2, c4 = f & 3;
            float4 va = *(const float4*)&A[(size_t)(m0 + r) * K + k0 + c4 * 4];
            uint32_t h0, h1, l0, l1;
            split2(va.x, va.y, h0, l0); split2(va.z, va.w, h1, l1);
            AsW[r * 20 + 2 * c4] = h0;      AsW[r * 20 + 2 * c4 + 1] = h1;
            AsW[r * 20 + 8 + 2 * c4] = l0;  AsW[r * 20 + 9 + 2 * c4] = l1;
            float4 vb = *(const float4*)&B[(size_t)(n0 + r) * K + k0 + c4 * 4];
            split2(vb.x, vb.y, h0, l0); split2(vb.z, vb.w, h1, l1);
            BsW[r * 20 + 2 * c4] = h0;      BsW[r * 20 + 2 * c4 + 1] = h1;
            BsW[r * 20 + 8 + 2 * c4] = l0;  BsW[r * 20 + 9 + 2 * c4] = l1;
        }
        __syncthreads();

        uint32_t ah[4][4], al[4][4], bh[4][2], bl[4][2];
        #pragma unroll
        for (int mt = 0; mt < 4; mt++) {
            int r = wm * 64 + mt * 16 + g;
            ah[mt][0] = AsW[r * 20 + tig];       ah[mt][1] = AsW[(r + 8) * 20 + tig];
            ah[mt][2] = AsW[r * 20 + 4 + tig];   ah[mt][3] = AsW[(r + 8) * 20 + 4 + tig];
            al[mt][0] = AsW[r * 20 + 8 + tig];   al[mt][1] = AsW[(r + 8) * 20 + 8 + tig];
            al[mt][2] = AsW[r * 20 + 12 + tig];  al[mt][3] = AsW[(r + 8) * 20 + 12 + tig];
        }
        #pragma unroll
        for (int nt = 0; nt < 4; nt++) {
            int rn = wn * 32 + nt * 8 + g;
            bh[nt][0] = BsW[rn * 20 + tig];      bh[nt][1] = BsW[rn * 20 + 4 + tig];
            bl[nt][0] = BsW[rn * 20 + 8 + tig];  bl[nt][1] = BsW[rn * 20 + 12 + tig];
        }
        #pragma unroll
        for (int mt = 0; mt < 4; mt++)
            #pragma unroll
            for (int nt = 0; nt < 4; nt++)
                MMAX3(c[mt][nt], ah[mt], al[mt], bh[nt][0], bh[nt][1], bl[nt][0], bl[nt][1]);
        __syncthreads();
    }

    #pragma unroll
    for (int mt = 0; mt < 4; mt++)
        #pragma unroll
        for (int nt = 0; nt < 4; nt++) {
            int r0 = m0 + wm * 64 + mt * 16 + g;
            int col = n0 + wn * 32 + nt * 8 + 2 * tig;
            *(float2*)&C[(size_t)r0 * N + col]       = make_float2(c[mt][nt][0], c[mt][nt][1]);
            *(float2*)&C[(size_t)(r0 + 8) * N + col] = make_float2(c[mt][nt][2], c[mt][nt][3]);
        }
}

// ======================================================================
// gemm_up<MODE>: same mainloop; epilogue writes bf16 hi/lo split tensors
// MODE 0: q (scale 0.125) -> H,L      MODE 1: kv -> H,L (k) / H2,L2 (v)
// ======================================================================
template<int MODE>
__global__ __launch_bounds__(256) void gemm_up(
    const float* __restrict__ A, const float* __restrict__ B,
    __nv_bfloat16* __restrict__ H,  __nv_bfloat16* __restrict__ L,
    __nv_bfloat16* __restrict__ H2, __nv_bfloat16* __restrict__ L2,
    int K, int N)
{
    __shared__ uint32_t AsW[128 * 20];
    __shared__ uint32_t BsW[128 * 20];
    const int tid = threadIdx.x;
    const int w = tid >> 5, lane = tid & 31;
    const int g = lane >> 2, tig = lane & 3;
    const int wm = w & 1, wn = w >> 1;
    const int m0 = blockIdx.y * 128, n0 = blockIdx.x * 128;

    float c[4][4][4] = {};

    for (int k0 = 0; k0 < K; k0 += 16) {
        #pragma unroll
        for (int p = 0; p < 2; p++) {
            int f = tid + p * 256, r = f >> 2, c4 = f & 3;
            float4 va = *(const float4*)&A[(size_t)(m0 + r) * K + k0 + c4 * 4];
            uint32_t h0, h1, l0, l1;
            split2(va.x, va.y, h0, l0); split2(va.z, va.w, h1, l1);
            AsW[r * 20 + 2 * c4] = h0;      AsW[r * 20 + 2 * c4 + 1] = h1;
            AsW[r * 20 + 8 + 2 * c4] = l0;  AsW[r * 20 + 9 + 2 * c4] = l1;
            float4 vb = *(const float4*)&B[(size_t)(n0 + r) * K + k0 + c4 * 4];
            split2(vb.x, vb.y, h0, l0); split2(vb.z, vb.w, h1, l1);
            BsW[r * 20 + 2 * c4] = h0;      BsW[r * 20 + 2 * c4 + 1] = h1;
            BsW[r * 20 + 8 + 2 * c4] = l0;  BsW[r * 20 + 9 + 2 * c4] = l1;
        }
        __syncthreads();

        uint32_t ah[4][4], al[4][4], bh[4][2], bl[4][2];
        #pragma unroll
        for (int mt = 0; mt < 4; mt++) {
            int r = wm * 64 + mt * 16 + g;
            ah[mt][0] = AsW[r * 20 + tig];       ah[mt][1] = AsW[(r + 8) * 20 + tig];
            ah[mt][2] = AsW[r * 20 + 4 + tig];   ah[mt][3] = AsW[(r + 8) * 20 + 4 + tig];
            al[mt][0] = AsW[r * 20 + 8 + tig];   al[mt][1] = AsW[(r + 8) * 20 + 8 + tig];
            al[mt][2] = AsW[r * 20 + 12 + tig];  al[mt][3] = AsW[(r + 8) * 20 + 12 + tig];
        }
        #pragma unroll
        for (int nt = 0; nt < 4; nt++) {
            int rn = wn * 32 + nt * 8 + g;
            bh[nt][0] = BsW[rn * 20 + tig];      bh[nt][1] = BsW[rn * 20 + 4 + tig];
            bl[nt][0] = BsW[rn * 20 + 8 + tig];  bl[nt][1] = BsW[rn * 20 + 12 + tig];
        }
        #pragma unroll
        for (int mt = 0; mt < 4; mt++)
            #pragma unroll
            for (int nt = 0; nt < 4; nt++)
                MMAX3(c[mt][nt], ah[mt], al[mt], bh[nt][0], bh[nt][1], bl[nt][0], bl[nt][1]);
        __syncthreads();
    }

    const float sc = (MODE == 0) ? 0.125f : 1.0f;
    #pragma unroll
    for (int mt = 0; mt < 4; mt++)
        #pragma unroll
        for (int nt = 0; nt < 4; nt++) {
            int tok = m0 + wm * 64 + mt * 16 + g;
            int col = n0 + wn * 32 + nt * 8 + 2 * tig;
            int b = tok >> 11, tn = tok & 2047;
            int h, d;
            __nv_bfloat16 *DH, *DL;
            if (MODE == 0) {
                h = col >> 6; d = col & 63; DH = H; DL = L;
            } else {
                h = col >> 7; int rr = col & 127; d = rr & 63;
                if (rr < 64) { DH = H; DL = L; } else { DH = H2; DL = L2; }
            }
            size_t a0 = (((size_t)b * 16 + h) * SEQ + tn) * 64 + d;
            size_t a1 = a0 + 8 * 64;
            uint32_t hp, lp;
            split2(c[mt][nt][0] * sc, c[mt][nt][1] * sc, hp, lp);
            *(uint32_t*)&DH[a0] = hp;  *(uint32_t*)&DL[a0] = lp;
            split2(c[mt][nt][2] * sc, c[mt][nt][3] * sc, hp, lp);
            *(uint32_t*)&DH[a1] = hp;  *(uint32_t*)&DL[a1] = lp;
        }
}

// ======================================================================
// gemm_lat: C[8192,64] = rmsnorm(A[8192,1024] @ W[64,1024]^T) * nw
// ======================================================================
__global__ __launch_bounds__(256) void gemm_lat(
    const float* __restrict__ A, const float* __restrict__ W,
    const float* __restrict__ nw, float* __restrict__ C)
{
    __shared__ uint32_t AsW[128 * 20];
    __shared__ uint32_t BsW[64 * 20];
    __shared__ float Cb[128][65];
    __shared__ float nws[64];
    const int tid = threadIdx.x;
    const int w = tid >> 5, lane = tid & 31;
    const int g = lane >> 2, tig = lane & 3;
    const int wm = w >> 1, wn = w & 1;
    const int m0 = blockIdx.x * 128;

    if (tid < 64) nws[tid] = nw[tid];

    float c[2][4][4] = {};

    for (int k0 = 0; k0 < 1024; k0 += 16) {
        #pragma unroll
        for (int p = 0; p < 2; p++) {
            int f = tid + p * 256, r = f >> 2, c4 = f & 3;
            float4 va = *(const float4*)&A[(size_t)(m0 + r) * 1024 + k0 + c4 * 4];
            uint32_t h0, h1, l0, l1;
            split2(va.x, va.y, h0, l0); split2(va.z, va.w, h1, l1);
            AsW[r * 20 + 2 * c4] = h0;      AsW[r * 20 + 2 * c4 + 1] = h1;
            AsW[r * 20 + 8 + 2 * c4] = l0;  AsW[r * 20 + 9 + 2 * c4] = l1;
        }
        {
            int r = tid >> 2, c4 = tid & 3;
            float4 vb = *(const float4*)&W[(size_t)r * 1024 + k0 + c4 * 4];
            uint32_t h0, h1, l0, l1;
            split2(vb.x, vb.y, h0, l0); split2(vb.z, vb.w, h1, l1);
            BsW[r * 20 + 2 * c4] = h0;      BsW[r * 20 + 2 * c4 + 1] = h1;
            BsW[r * 20 + 8 + 2 * c4] = l0;  BsW[r * 20 + 9 + 2 * c4] = l1;
        }
        __syncthreads();

        uint32_t ah[2][4], al[2][4], bh[4][2], bl[4][2];
        #pragma unroll
        for (int mt = 0; mt < 2; mt++) {
            int r = wm * 32 + mt * 16 + g;
            ah[mt][0] = AsW[r * 20 + tig];       ah[mt][1] = AsW[(r + 8) * 20 + tig];
            ah[mt][2] = AsW[r * 20 + 4 + tig];   ah[mt][3] = AsW[(r + 8) * 20 + 4 + tig];
            al[mt][0] = AsW[r * 20 + 8 + tig];   al[mt][1] = AsW[(r + 8) * 20 + 8 + tig];
            al[mt][2] = AsW[r * 20 + 12 + tig];  al[mt][3] = AsW[(r + 8) * 20 + 12 + tig];
        }
        #pragma unroll
        for (int nt = 0; nt < 4; nt++) {
            int rn = wn * 32 + nt * 8 + g;
            bh[nt][0] = BsW[rn * 20 + tig];      bh[nt][1] = BsW[rn * 20 + 4 + tig];
            bl[nt][0] = BsW[rn * 20 + 8 + tig];  bl[nt][1] = BsW[rn * 20 + 12 + tig];
        }
        #pragma unroll
        for (int mt = 0; mt < 2; mt++)
            #pragma unroll
            for (int nt = 0; nt < 4; nt++)
                MMAX3(c[mt][nt], ah[mt], al[mt], bh[nt][0], bh[nt][1], bl[nt][0], bl[nt][1]);
        __syncthreads();
    }

    #pragma unroll
    for (int mt = 0; mt < 2; mt++)
        #pragma unroll
        for (int nt = 0; nt < 4; nt++) {
            int rr = wm * 32 + mt * 16 + g, col = wn * 32 + nt * 8 + 2 * tig;
            Cb[rr][col]     = c[mt][nt][0];  Cb[rr][col + 1]     = c[mt][nt][1];
            Cb[rr + 8][col] = c[mt][nt][2];  Cb[rr + 8][col + 1] = c[mt][nt][3];
        }
    __syncthreads();

    if (tid < 128) {
        float v[64], ss = 0.f;
        #pragma unroll
        for (int j = 0; j < 64; j++) { v[j] = Cb[tid][j]; ss += v[j] * v[j]; }
        float scl = rsqrtf(ss * (1.0f / 64.0f) + 1e-6f);
        float* dst = &C[(size_t)(m0 + tid) * 64];
        #pragma unroll
        for (int j = 0; j < 64; j += 4)
            *(float4*)&dst[j] = make_float4(v[j] * scl * nws[j],   v[j+1] * scl * nws[j+1],
                                            v[j+2] * scl * nws[j+2], v[j+3] * scl * nws[j+3]);
    }
}

// ======================================================================
// attn_tc: flash attention, bf16x3 mma.sync, ldmatrix fragments,
// cp.async double-buffered K/V, P kept in registers (C-frag == A-frag).
// ======================================================================
#define ATTN_SMEM 163840

__global__ __launch_bounds__(256, 1) void attn_tc(
    const __nv_bfloat16* __restrict__ qh_g, const __nv_bfloat16* __restrict__ ql_g,
    const __nv_bfloat16* __restrict__ kh_g, const __nv_bfloat16* __restrict__ kl_g,
    const __nv_bfloat16* __restrict__ vh_g, const __nv_bfloat16* __restrict__ vl_g,
    float* __restrict__ yf)
{
    extern __shared__ char smraw[];
    const uint32_t base = smem_u32(smraw);
    const uint32_t Qh = base, Ql = base + 16384;
    const uint32_t KhB[2] = { base + 32768,  base + 98304 };
    const uint32_t KlB[2] = { base + 49152,  base + 114688 };
    const uint32_t VhB[2] = { base + 65536,  base + 131072 };
    const uint32_t VlB[2] = { base + 81920,  base + 147456 };

    const int tid = threadIdx.x;
    const int w = tid >> 5, lane = tid & 31;
    const int g = lane >> 2, tig = lane & 3;
    const int l8 = lane & 7, sub = lane >> 3;
    const int r0 = w * 16;
    const int bh = blockIdx.y;
    const int q0 = blockIdx.x * 128;
    const size_t hb = (size_t)bh * SEQ;   // head-row base in split tensors

    // ---- stage Q + chunk0 (group 0), chunk1 (group 1) ----
    #pragma unroll
    for (int p = 0; p < 4; p++) {
        int idx = tid + p * 256, row = idx >> 3, ch = idx & 7;
        size_t go = (hb + q0 + row) * 64 + ch * 8;
        CPA16(lda(Qh, row, ch), qh_g + go);
        CPA16(lda(Ql, row, ch), ql_g + go);
    }
    #pragma unroll
    for (int p = 0; p < 4; p++) {
        int idx = tid + p * 256, row = idx >> 3, ch = idx & 7;
        size_t go = (hb + row) * 64 + ch * 8;
        uint32_t so = (uint32_t)row * 128 + (((uint32_t)ch ^ ((uint32_t)row & 7u)) << 4);
        CPA16(KhB[0] + so, kh_g + go);  CPA16(KlB[0] + so, kl_g + go);
        CPA16(VhB[0] + so, vh_g + go);  CPA16(VlB[0] + so, vl_g + go);
    }
    CPCOMMIT();
    #pragma unroll
    for (int p = 0; p < 4; p++) {
        int idx = tid + p * 256, row = idx >> 3, ch = idx & 7;
        size_t go = (hb + 128 + row) * 64 + ch * 8;
        uint32_t so = (uint32_t)row * 128 + (((uint32_t)ch ^ ((uint32_t)row & 7u)) << 4);
        CPA16(KhB[1] + so, kh_g + go);  CPA16(KlB[1] + so, kl_g + go);
        CPA16(VhB[1] + so, vh_g + go);  CPA16(VlB[1] + so, vl_g + go);
    }
    CPCOMMIT();

    float o[8][4] = {};
    float lsum0 = 0.f, lsum1 = 0.f;

    for (int kc = 0; kc < 16; kc++) {
        const int bi = kc & 1;
        if (kc == 15) { CPWAIT(0); } else { CPWAIT(1); }
        __syncthreads();

        // ---- S = Q @ K^T (fp32 accum, bf16x3) ----
        float s[16][4] = {};
        #pragma unroll
        for (int ks = 0; ks < 4; ks++) {
            int arow = r0 + l8 + ((sub & 1) << 3);
            int ach  = 2 * ks + (sub >> 1);
            uint32_t ah[4], al[4];
            LDSM4(ah, lda(Qh, arow, ach));
            LDSM4(al, lda(Ql, arow, ach));
            #pragma unroll
            for (int ntp = 0; ntp < 8; ntp++) {
                int krow = ntp * 16 + ((sub >> 1) << 3) + l8;
                int kch  = 2 * ks + (sub & 1);
                uint32_t bhf[4], blf[4];
                LDSM4(bhf, lda(KhB[bi], krow, kch));
                LDSM4(blf, lda(KlB[bi], krow, kch));
                MMAX3(s[2 * ntp],     ah, al, bhf[0], bhf[1], blf[0], blf[1]);
                MMAX3(s[2 * ntp + 1], ah, al, bhf[2], bhf[3], blf[2], blf[3]);
            }
        }

        // ---- exp + pack into PV A-fragments (registers only) ----
        uint32_t ph[8][4], pl[8][4];
        #pragma unroll
        for (int kp = 0; kp < 8; kp++) {
            float e0 = __expf(s[2*kp][0]),   e1 = __expf(s[2*kp][1]);
            float e2 = __expf(s[2*kp][2]),   e3 = __expf(s[2*kp][3]);
            float e4 = __expf(s[2*kp+1][0]), e5 = __expf(s[2*kp+1][1]);
            float e6 = __expf(s[2*kp+1][2]), e7 = __expf(s[2*kp+1][3]);
            lsum0 += e0 + e1 + e4 + e5;
            lsum1 += e2 + e3 + e6 + e7;
            split2(e0, e1, ph[kp][0], pl[kp][0]);
            split2(e2, e3, ph[kp][1], pl[kp][1]);
            split2(e4, e5, ph[kp][2], pl[kp][2]);
            split2(e6, e7, ph[kp][3], pl[kp][3]);
        }

        // ---- O += P @ V (V via ldmatrix.trans) ----
        #pragma unroll
        for (int ks = 0; ks < 8; ks++) {
            #pragma unroll
            for (int ntp = 0; ntp < 4; ntp++) {
                int vrow = ks * 16 + ((sub & 1) << 3) + l8;
                int vch  = 2 * ntp + (sub >> 1);
                uint32_t vhf[4], vlf[4];
                LDSM4T(vhf, lda(VhB[bi], vrow, vch));
                LDSM4T(vlf, lda(VlB[bi], vrow, vch));
                MMAX3(o[2 * ntp],     ph[ks], pl[ks], vhf[0], vhf[1], vlf[0], vlf[1]);
                MMAX3(o[2 * ntp + 1], ph[ks], pl[ks], vhf[2], vhf[3], vlf[2], vlf[3]);
            }
        }

        __syncthreads();
        // ---- prefetch chunk kc+2 into the buffer we just finished ----
        if (kc + 2 < 16) {
            #pragma unroll
            for (int p = 0; p < 4; p++) {
                int idx = tid + p * 256, row = idx >> 3, ch = idx & 7;
                size_t go = (hb + (kc + 2) * 128 + row) * 64 + ch * 8;
                uint32_t so = (uint32_t)row * 128 + (((uint32_t)ch ^ ((uint32_t)row & 7u)) << 4);
                CPA16(KhB[bi] + so, kh_g + go);  CPA16(KlB[bi] + so, kl_g + go);
                CPA16(VhB[bi] + so, vh_g + go);  CPA16(VlB[bi] + so, vl_g + go);
            }
        }
        CPCOMMIT();
    }

    // reduce row sums over the 4 tig lanes
    lsum0 += __shfl_xor_sync(0xffffffffu, lsum0, 1);
    lsum0 += __shfl_xor_sync(0xffffffffu, lsum0, 2);
    lsum1 += __shfl_xor_sync(0xffffffffu, lsum1, 1);
    lsum1 += __shfl_xor_sync(0xffffffffu, lsum1, 2);
    float inv0 = 1.0f / lsum0, inv1 = 1.0f / lsum1;

    const int b = bh >> 4, h = bh & 15;
    float* y0 = yf + ((size_t)b * SEQ + q0 + r0 + g) * 1024 + h * 64;
    float* y1 = yf + ((size_t)b * SEQ + q0 + r0 + g + 8) * 1024 + h * 64;
    #pragma unroll
    for (int nt = 0; nt < 8; nt++) {
        int col = nt * 8 + 2 * tig;
        *(float2*)&y0[col] = make_float2(o[nt][0] * inv0, o[nt][1] * inv0);
        *(float2*)&y1[col] = make_float2(o[nt][2] * inv1, o[nt][3] * inv1);
    }
}

// ---------------------------------------------------------------------------
extern "C" void kernel_launch(void* const* d_in, const int* in_sizes, int n_in,
                              void* d_out, int out_size)
{
    const float* x      = (const float*)d_in[0];
    const float* w_kv_a = (const float*)d_in[1];
    const float* w_kv_b = (const float*)d_in[2];
    const float* w_q_a  = (const float*)d_in[3];
    const float* w_q_b  = (const float*)d_in[4];
    const float* w_proj = (const float*)d_in[5];
    const float* kv_nw  = (const float*)d_in[6];
    const float* q_nw   = (const float*)d_in[7];
    float* out = (float*)d_out;

    float *qlat, *kvlat, *y;
    __nv_bfloat16 *qh, *ql, *kh, *kl, *vh, *vl;
    cudaGetSymbolAddress((void**)&qlat,  g_qlat);
    cudaGetSymbolAddress((void**)&kvlat, g_kvlat);
    cudaGetSymbolAddress((void**)&y,     g_y);
    cudaGetSymbolAddress((void**)&qh, g_qh);  cudaGetSymbolAddress((void**)&ql, g_ql);
    cudaGetSymbolAddress((void**)&kh, g_kh);  cudaGetSymbolAddress((void**)&kl, g_kl);
    cudaGetSymbolAddress((void**)&vh, g_vh);  cudaGetSymbolAddress((void**)&vl, g_vl);

    cudaFuncSetAttribute(attn_tc,
                         cudaFuncAttributeMaxDynamicSharedMemorySize, ATTN_SMEM);

    // latent projections + fused rmsnorm
    gemm_lat<<<64, 256>>>(x, w_q_a,  q_nw,  qlat);
    gemm_lat<<<64, 256>>>(x, w_kv_a, kv_nw, kvlat);

    // up-projections -> bf16 hi/lo split, per-head layout
    gemm_up<0><<<dim3(8, 64),  256>>>(qlat,  w_q_b,  qh, ql, nullptr, nullptr, 64, 1024);
    gemm_up<1><<<dim3(16, 64), 256>>>(kvlat, w_kv_b, kh, kl, vh, vl, 64, 2048);

    // attention
    attn_tc<<<dim3(16, 64), 256, ATTN_SMEM>>>(qh, ql, kh, kl, vh, vl, y);

    // output projection
    gemm_tc<<<dim3(8, 64), 256>>>(y, w_proj, out, 1024, 1024);
}

// round 5
// speedup vs baseline: 2.7033x; 1.0061x over previous
#include <cuda_runtime.h>
#include <cuda_bf16.h>
#include <cstdint>

#define SEQ   2048
#define NTOK  8192

// ---------------- scratch (device globals: no runtime allocation) ----------
__device__ float g_qlat [(size_t)NTOK * 64];
__device__ float g_kvlat[(size_t)NTOK * 64];
__device__ float g_y  [(size_t)NTOK * 1024];
// bf16 hi/lo split tensors, per-head layout [(b*16+h)][seq][64]
__device__ __nv_bfloat16 g_qh[(size_t)NTOK * 1024];
__device__ __nv_bfloat16 g_ql[(size_t)NTOK * 1024];
__device__ __nv_bfloat16 g_kh[(size_t)NTOK * 1024];
__device__ __nv_bfloat16 g_kl[(size_t)NTOK * 1024];
__device__ __nv_bfloat16 g_vh[(size_t)NTOK * 1024];
__device__ __nv_bfloat16 g_vl[(size_t)NTOK * 1024];

// ---------------- helpers ---------------------------------------------------
static __device__ __forceinline__ uint32_t smem_u32(const void* p) {
    uint32_t a;
    asm("{ .reg .u64 t; cvta.to.shared.u64 t, %1; cvt.u32.u64 %0, t; }"
        : "=r"(a) : "l"(p));
    return a;
}
static __device__ __forceinline__ uint32_t bfpack(float lo, float hi) {
    uint32_t r;
    asm("cvt.rn.bf16x2.f32 %0, %1, %2;" : "=r"(r) : "f"(hi), "f"(lo));
    return r;
}
static __device__ __forceinline__ void split2(float x, float y,
                                              uint32_t& h, uint32_t& l) {
    h = bfpack(x, y);
    __nv_bfloat162 hb = *reinterpret_cast<__nv_bfloat162*>(&h);
    l = bfpack(x - __bfloat162float(hb.x), y - __bfloat162float(hb.y));
}
// swizzled smem addr: 128B rows of 8 x 16B chunks, chunk ^= row&7
static __device__ __forceinline__ uint32_t lda(uint32_t base, int row, int ch) {
    return base + row * 128 + (((uint32_t)ch ^ ((uint32_t)row & 7u)) << 4);
}

#define MMAB(c, a0, a1, a2, a3, b0, b1)                                        \
    asm volatile("mma.sync.aligned.m16n8k16.row.col.f32.bf16.bf16.f32 "        \
        "{%0,%1,%2,%3},{%4,%5,%6,%7},{%8,%9},{%0,%1,%2,%3};"                   \
        : "+f"((c)[0]), "+f"((c)[1]), "+f"((c)[2]), "+f"((c)[3])               \
        : "r"(a0), "r"(a1), "r"(a2), "r"(a3), "r"(b0), "r"(b1))

#define MMAX3(c, ah, al, bh0, bh1, bl0, bl1) do {                              \
    MMAB(c, (ah)[0], (ah)[1], (ah)[2], (ah)[3], bh0, bh1);                     \
    MMAB(c, (ah)[0], (ah)[1], (ah)[2], (ah)[3], bl0, bl1);                     \
    MMAB(c, (al)[0], (al)[1], (al)[2], (al)[3], bh0, bh1);                     \
} while (0)

#define LDSM4(r, addr)                                                         \
    asm volatile("ldmatrix.sync.aligned.m8n8.x4.shared.b16 {%0,%1,%2,%3}, [%4];" \
        : "=r"((r)[0]), "=r"((r)[1]), "=r"((r)[2]), "=r"((r)[3]) : "r"(addr))
#define LDSM4T(r, addr)                                                        \
    asm volatile("ldmatrix.sync.aligned.m8n8.x4.trans.shared.b16 {%0,%1,%2,%3}, [%4];" \
        : "=r"((r)[0]), "=r"((r)[1]), "=r"((r)[2]), "=r"((r)[3]) : "r"(addr))
#define CPA16(dst, src)                                                        \
    asm volatile("cp.async.cg.shared.global [%0], [%1], 16;" :: "r"(dst), "l"(src))
#define CPCOMMIT() asm volatile("cp.async.commit_group;" ::: "memory")
#define CPWAIT(n)  asm volatile("cp.async.wait_group %0;" :: "n"(n) : "memory")

// ======================================================================
// gemm_tc: C[M,N] = A[M,K] @ B[N,K]^T   bf16x3 mma.sync (fp32 out)
// ======================================================================
__global__ __launch_bounds__(256, 2) void gemm_tc(
    const float* __restrict__ A, const float* __restrict__ B,
    float* __restrict__ C, int K, int N)
{
    __shared__ uint32_t AsW[128 * 20];
    __shared__ uint32_t BsW[128 * 20];
    const int tid = threadIdx.x;
    const int w = tid >> 5, lane = tid & 31;
    const int g = lane >> 2, tig = lane & 3;
    const int wm = w & 1, wn = w >> 1;
    const int m0 = blockIdx.y * 128, n0 = blockIdx.x * 128;

    float c[4][4][4] = {};

    for (int k0 = 0; k0 < K; k0 += 16) {
        #pragma unroll
        for (int p = 0; p < 2; p++) {
            int f = tid + p * 256, r = f >> 2, c4 = f & 3;
            float4 va = *(const float4*)&A[(size_t)(m0 + r) * K + k0 + c4 * 4];
            uint32_t h0, h1, l0, l1;
            split2(va.x, va.y, h0, l0); split2(va.z, va.w, h1, l1);
            AsW[r * 20 + 2 * c4] = h0;      AsW[r * 20 + 2 * c4 + 1] = h1;
            AsW[r * 20 + 8 + 2 * c4] = l0;  AsW[r * 20 + 9 + 2 * c4] = l1;
            float4 vb = *(const float4*)&B[(size_t)(n0 + r) * K + k0 + c4 * 4];
            split2(vb.x, vb.y, h0, l0); split2(vb.z, vb.w, h1, l1);
            BsW[r * 20 + 2 * c4] = h0;      BsW[r * 20 + 2 * c4 + 1] = h1;
            BsW[r * 20 + 8 + 2 * c4] = l0;  BsW[r * 20 + 9 + 2 * c4] = l1;
        }
        __syncthreads();

        uint32_t ah[4][4], al[4][4], bh[4][2], bl[4][2];
        #pragma unroll
        for (int mt = 0; mt < 4; mt++) {
            int r = wm * 64 + mt * 16 + g;
            ah[mt][0] = AsW[r * 20 + tig];       ah[mt][1] = AsW[(r + 8) * 20 + tig];
            ah[mt][2] = AsW[r * 20 + 4 + tig];   ah[mt][3] = AsW[(r + 8) * 20 + 4 + tig];
            al[mt][0] = AsW[r * 20 + 8 + tig];   al[mt][1] = AsW[(r + 8) * 20 + 8 + tig];
            al[mt][2] = AsW[r * 20 + 12 + tig];  al[mt][3] = AsW[(r + 8) * 20 + 12 + tig];
        }
        #pragma unroll
        for (int nt = 0; nt < 4; nt++) {
            int rn = wn * 32 + nt * 8 + g;
            bh[nt][0] = BsW[rn * 20 + tig];      bh[nt][1] = BsW[rn * 20 + 4 + tig];
            bl[nt][0] = BsW[rn * 20 + 8 + tig];  bl[nt][1] = BsW[rn * 20 + 12 + tig];
        }
        #pragma unroll
        for (int mt = 0; mt < 4; mt++)
            #pragma unroll
            for (int nt = 0; nt < 4; nt++)
                MMAX3(c[mt][nt], ah[mt], al[mt], bh[nt][0], bh[nt][1], bl[nt][0], bl[nt][1]);
        __syncthreads();
    }

    #pragma unroll
    for (int mt = 0; mt < 4; mt++)
        #pragma unroll
        for (int nt = 0; nt < 4; nt++) {
            int r0 = m0 + wm * 64 + mt * 16 + g;
            int col = n0 + wn * 32 + nt * 8 + 2 * tig;
            *(float2*)&C[(size_t)r0 * N + col]       = make_float2(c[mt][nt][0], c[mt][nt][1]);
            *(float2*)&C[(size_t)(r0 + 8) * N + col] = make_float2(c[mt][nt][2], c[mt][nt][3]);
        }
}

// ======================================================================
// gemm_up<MODE>: same mainloop; epilogue writes bf16 hi/lo split tensors
// MODE 0: q (scale 0.125) -> H,L      MODE 1: kv -> H,L (k) / H2,L2 (v)
// ======================================================================
template<int MODE>
__global__ __launch_bounds__(256, 2) void gemm_up(
    const float* __restrict__ A, const float* __restrict__ B,
    __nv_bfloat16* __restrict__ H,  __nv_bfloat16* __restrict__ L,
    __nv_bfloat16* __restrict__ H2, __nv_bfloat16* __restrict__ L2,
    int K, int N)
{
    __shared__ uint32_t AsW[128 * 20];
    __shared__ uint32_t BsW[128 * 20];
    const int tid = threadIdx.x;
    const int w = tid >> 5, lane = tid & 31;
    const int g = lane >> 2, tig = lane & 3;
    const int wm = w & 1, wn = w >> 1;
    const int m0 = blockIdx.y * 128, n0 = blockIdx.x * 128;

    float c[4][4][4] = {};

    for (int k0 = 0; k0 < K; k0 += 16) {
        #pragma unroll
        for (int p = 0; p < 2; p++) {
            int f = tid + p * 256, r = f >> 2, c4 = f & 3;
            float4 va = *(const float4*)&A[(size_t)(m0 + r) * K + k0 + c4 * 4];
            uint32_t h0, h1, l0, l1;
            split2(va.x, va.y, h0, l0); split2(va.z, va.w, h1, l1);
            AsW[r * 20 + 2 * c4] = h0;      AsW[r * 20 + 2 * c4 + 1] = h1;
            AsW[r * 20 + 8 + 2 * c4] = l0;  AsW[r * 20 + 9 + 2 * c4] = l1;
            float4 vb = *(const float4*)&B[(size_t)(n0 + r) * K + k0 + c4 * 4];
            split2(vb.x, vb.y, h0, l0); split2(vb.z, vb.w, h1, l1);
            BsW[r * 20 + 2 * c4] = h0;      BsW[r * 20 + 2 * c4 + 1] = h1;
            BsW[r * 20 + 8 + 2 * c4] = l0;  BsW[r * 20 + 9 + 2 * c4] = l1;
        }
        __syncthreads();

        uint32_t ah[4][4], al[4][4], bh[4][2], bl[4][2];
        #pragma unroll
        for (int mt = 0; mt < 4; mt++) {
            int r = wm * 64 + mt * 16 + g;
            ah[mt][0] = AsW[r * 20 + tig];       ah[mt][1] = AsW[(r + 8) * 20 + tig];
            ah[mt][2] = AsW[r * 20 + 4 + tig];   ah[mt][3] = AsW[(r + 8) * 20 + 4 + tig];
            al[mt][0] = AsW[r * 20 + 8 + tig];   al[mt][1] = AsW[(r + 8) * 20 + 8 + tig];
            al[mt][2] = AsW[r * 20 + 12 + tig];  al[mt][3] = AsW[(r + 8) * 20 + 12 + tig];
        }
        #pragma unroll
        for (int nt = 0; nt < 4; nt++) {
            int rn = wn * 32 + nt * 8 + g;
            bh[nt][0] = BsW[rn * 20 + tig];      bh[nt][1] = BsW[rn * 20 + 4 + tig];
            bl[nt][0] = BsW[rn * 20 + 8 + tig];  bl[nt][1] = BsW[rn * 20 + 12 + tig];
        }
        #pragma unroll
        for (int mt = 0; mt < 4; mt++)
            #pragma unroll
            for (int nt = 0; nt < 4; nt++)
                MMAX3(c[mt][nt], ah[mt], al[mt], bh[nt][0], bh[nt][1], bl[nt][0], bl[nt][1]);
        __syncthreads();
    }

    const float sc = (MODE == 0) ? 0.125f : 1.0f;
    #pragma unroll
    for (int mt = 0; mt < 4; mt++)
        #pragma unroll
        for (int nt = 0; nt < 4; nt++) {
            int tok = m0 + wm * 64 + mt * 16 + g;
            int col = n0 + wn * 32 + nt * 8 + 2 * tig;
            int b = tok >> 11, tn = tok & 2047;
            int h, d;
            __nv_bfloat16 *DH, *DL;
            if (MODE == 0) {
                h = col >> 6; d = col & 63; DH = H; DL = L;
            } else {
                h = col >> 7; int rr = col & 127; d = rr & 63;
                if (rr < 64) { DH = H; DL = L; } else { DH = H2; DL = L2; }
            }
            size_t a0 = (((size_t)b * 16 + h) * SEQ + tn) * 64 + d;
            size_t a1 = a0 + 8 * 64;
            uint32_t hp, lp;
            split2(c[mt][nt][0] * sc, c[mt][nt][1] * sc, hp, lp);
            *(uint32_t*)&DH[a0] = hp;  *(uint32_t*)&DL[a0] = lp;
            split2(c[mt][nt][2] * sc, c[mt][nt][3] * sc, hp, lp);
            *(uint32_t*)&DH[a1] = hp;  *(uint32_t*)&DL[a1] = lp;
        }
}

// ======================================================================
// gemm_lat: C[8192,64] = rmsnorm(A[8192,1024] @ W[64,1024]^T) * nw
// ======================================================================
__global__ __launch_bounds__(256, 2) void gemm_lat(
    const float* __restrict__ A, const float* __restrict__ W,
    const float* __restrict__ nw, float* __restrict__ C)
{
    __shared__ uint32_t AsW[128 * 20];
    __shared__ uint32_t BsW[64 * 20];
    __shared__ float Cb[128][65];
    __shared__ float nws[64];
    const int tid = threadIdx.x;
    const int w = tid >> 5, lane = tid & 31;
    const int g = lane >> 2, tig = lane & 3;
    const int wm = w >> 1, wn = w & 1;
    const int m0 = blockIdx.x * 128;

    if (tid < 64) nws[tid] = nw[tid];

    float c[2][4][4] = {};

    for (int k0 = 0; k0 < 1024; k0 += 16) {
        #pragma unroll
        for (int p = 0; p < 2; p++) {
            int f = tid + p * 256, r = f >> 2, c4 = f & 3;
            float4 va = *(const float4*)&A[(size_t)(m0 + r) * 1024 + k0 + c4 * 4];
            uint32_t h0, h1, l0, l1;
            split2(va.x, va.y, h0, l0); split2(va.z, va.w, h1, l1);
            AsW[r * 20 + 2 * c4] = h0;      AsW[r * 20 + 2 * c4 + 1] = h1;
            AsW[r * 20 + 8 + 2 * c4] = l0;  AsW[r * 20 + 9 + 2 * c4] = l1;
        }
        {
            int r = tid >> 2, c4 = tid & 3;
            float4 vb = *(const float4*)&W[(size_t)r * 1024 + k0 + c4 * 4];
            uint32_t h0, h1, l0, l1;
            split2(vb.x, vb.y, h0, l0); split2(vb.z, vb.w, h1, l1);
            BsW[r * 20 + 2 * c4] = h0;      BsW[r * 20 + 2 * c4 + 1] = h1;
            BsW[r * 20 + 8 + 2 * c4] = l0;  BsW[r * 20 + 9 + 2 * c4] = l1;
        }
        __syncthreads();

        uint32_t ah[2][4], al[2][4], bh[4][2], bl[4][2];
        #pragma unroll
        for (int mt = 0; mt < 2; mt++) {
            int r = wm * 32 + mt * 16 + g;
            ah[mt][0] = AsW[r * 20 + tig];       ah[mt][1] = AsW[(r + 8) * 20 + tig];
            ah[mt][2] = AsW[r * 20 + 4 + tig];   ah[mt][3] = AsW[(r + 8) * 20 + 4 + tig];
            al[mt][0] = AsW[r * 20 + 8 + tig];   al[mt][1] = AsW[(r + 8) * 20 + 8 + tig];
            al[mt][2] = AsW[r * 20 + 12 + tig];  al[mt][3] = AsW[(r + 8) * 20 + 12 + tig];
        }
        #pragma unroll
        for (int nt = 0; nt < 4; nt++) {
            int rn = wn * 32 + nt * 8 + g;
            bh[nt][0] = BsW[rn * 20 + tig];      bh[nt][1] = BsW[rn * 20 + 4 + tig];
            bl[nt][0] = BsW[rn * 20 + 8 + tig];  bl[nt][1] = BsW[rn * 20 + 12 + tig];
        }
        #pragma unroll
        for (int mt = 0; mt < 2; mt++)
            #pragma unroll
            for (int nt = 0; nt < 4; nt++)
                MMAX3(c[mt][nt], ah[mt], al[mt], bh[nt][0], bh[nt][1], bl[nt][0], bl[nt][1]);
        __syncthreads();
    }

    #pragma unroll
    for (int mt = 0; mt < 2; mt++)
        #pragma unroll
        for (int nt = 0; nt < 4; nt++) {
            int rr = wm * 32 + mt * 16 + g, col = wn * 32 + nt * 8 + 2 * tig;
            Cb[rr][col]     = c[mt][nt][0];  Cb[rr][col + 1]     = c[mt][nt][1];
            Cb[rr + 8][col] = c[mt][nt][2];  Cb[rr + 8][col + 1] = c[mt][nt][3];
        }
    __syncthreads();

    if (tid < 128) {
        float v[64], ss = 0.f;
        #pragma unroll
        for (int j = 0; j < 64; j++) { v[j] = Cb[tid][j]; ss += v[j] * v[j]; }
        float scl = rsqrtf(ss * (1.0f / 64.0f) + 1e-6f);
        float* dst = &C[(size_t)(m0 + tid) * 64];
        #pragma unroll
        for (int j = 0; j < 64; j += 4)
            *(float4*)&dst[j] = make_float4(v[j] * scl * nws[j],   v[j+1] * scl * nws[j+1],
                                            v[j+2] * scl * nws[j+2], v[j+3] * scl * nws[j+3]);
    }
}

// ======================================================================
// attn_tc: flash attention, bf16x3 mma.sync, ldmatrix fragments.
// Single-buffered K/V (96KB smem) + <=128 regs -> 2 CTAs/SM.
// exp+PV interleaved per 16-key group: no P fragment arrays.
// ======================================================================
#define ATTN_SMEM 98304

__global__ __launch_bounds__(256, 2) void attn_tc(
    const __nv_bfloat16* __restrict__ qh_g, const __nv_bfloat16* __restrict__ ql_g,
    const __nv_bfloat16* __restrict__ kh_g, const __nv_bfloat16* __restrict__ kl_g,
    const __nv_bfloat16* __restrict__ vh_g, const __nv_bfloat16* __restrict__ vl_g,
    float* __restrict__ yf)
{
    extern __shared__ char smraw[];
    const uint32_t base = smem_u32(smraw);
    const uint32_t Qh = base,          Ql = base + 16384;
    const uint32_t Kh = base + 32768,  Kl = base + 49152;
    const uint32_t Vh = base + 65536,  Vl = base + 81920;

    const int tid = threadIdx.x;
    const int w = tid >> 5, lane = tid & 31;
    const int g = lane >> 2, tig = lane & 3;
    const int l8 = lane & 7, sub = lane >> 3;
    const int r0 = w * 16;
    const int bh = blockIdx.y;
    const int q0 = blockIdx.x * 128;
    const size_t hb = (size_t)bh * SEQ;

    // ---- stage Q + chunk 0 ----
    #pragma unroll
    for (int p = 0; p < 4; p++) {
        int idx = tid + p * 256, row = idx >> 3, ch = idx & 7;
        size_t go = (hb + q0 + row) * 64 + ch * 8;
        CPA16(lda(Qh, row, ch), qh_g + go);
        CPA16(lda(Ql, row, ch), ql_g + go);
    }
    #pragma unroll
    for (int p = 0; p < 4; p++) {
        int idx = tid + p * 256, row = idx >> 3, ch = idx & 7;
        size_t go = (hb + row) * 64 + ch * 8;
        uint32_t so = (uint32_t)row * 128 + (((uint32_t)ch ^ ((uint32_t)row & 7u)) << 4);
        CPA16(Kh + so, kh_g + go);  CPA16(Kl + so, kl_g + go);
        CPA16(Vh + so, vh_g + go);  CPA16(Vl + so, vl_g + go);
    }
    CPCOMMIT();
    CPWAIT(0);
    __syncthreads();

    float o[8][4] = {};
    float lsum0 = 0.f, lsum1 = 0.f;

    for (int kc = 0; kc < 16; kc++) {
        // ---- S = Q @ K^T (fp32 accum, bf16x3) ----
        float s[16][4] = {};
        #pragma unroll
        for (int ks = 0; ks < 4; ks++) {
            int arow = r0 + l8 + ((sub & 1) << 3);
            int ach  = 2 * ks + (sub >> 1);
            uint32_t ah[4], al[4];
            LDSM4(ah, lda(Qh, arow, ach));
            LDSM4(al, lda(Ql, arow, ach));
            #pragma unroll
            for (int ntp = 0; ntp < 8; ntp++) {
                int krow = ntp * 16 + ((sub >> 1) << 3) + l8;
                int kch  = 2 * ks + (sub & 1);
                uint32_t bhf[4], blf[4];
                LDSM4(bhf, lda(Kh, krow, kch));
                LDSM4(blf, lda(Kl, krow, kch));
                MMAX3(s[2 * ntp],     ah, al, bhf[0], bhf[1], blf[0], blf[1]);
                MMAX3(s[2 * ntp + 1], ah, al, bhf[2], bhf[3], blf[2], blf[3]);
            }
        }

        // ---- exp + PV per 16-key group (P fragments transient) ----
        #pragma unroll
        for (int ks = 0; ks < 8; ks++) {
            float e0 = __expf(s[2*ks][0]),   e1 = __expf(s[2*ks][1]);
            float e2 = __expf(s[2*ks][2]),   e3 = __expf(s[2*ks][3]);
            float e4 = __expf(s[2*ks+1][0]), e5 = __expf(s[2*ks+1][1]);
            float e6 = __expf(s[2*ks+1][2]), e7 = __expf(s[2*ks+1][3]);
            lsum0 += e0 + e1 + e4 + e5;
            lsum1 += e2 + e3 + e6 + e7;
            uint32_t ph[4], pl[4];
            split2(e0, e1, ph[0], pl[0]);
            split2(e2, e3, ph[1], pl[1]);
            split2(e4, e5, ph[2], pl[2]);
            split2(e6, e7, ph[3], pl[3]);
            #pragma unroll
            for (int ntp = 0; ntp < 4; ntp++) {
                int vrow = ks * 16 + ((sub & 1) << 3) + l8;
                int vch  = 2 * ntp + (sub >> 1);
                uint32_t vhf[4], vlf[4];
                LDSM4T(vhf, lda(Vh, vrow, vch));
                LDSM4T(vlf, lda(Vl, vrow, vch));
                MMAX3(o[2 * ntp],     ph, pl, vhf[0], vhf[1], vlf[0], vlf[1]);
                MMAX3(o[2 * ntp + 1], ph, pl, vhf[2], vhf[3], vlf[2], vlf[3]);
            }
        }

        // ---- restage next chunk into the single buffer ----
        if (kc < 15) {
            __syncthreads();
            #pragma unroll
            for (int p = 0; p < 4; p++) {
                int idx = tid + p * 256, row = idx >> 3, ch = idx & 7;
                size_t go = (hb + (kc + 1) * 128 + row) * 64 + ch * 8;
                uint32_t so = (uint32_t)row * 128 + (((uint32_t)ch ^ ((uint32_t)row & 7u)) << 4);
                CPA16(Kh + so, kh_g + go);  CPA16(Kl + so, kl_g + go);
                CPA16(Vh + so, vh_g + go);  CPA16(Vl + so, vl_g + go);
            }
            CPCOMMIT();
            CPWAIT(0);
            __syncthreads();
        }
    }

    // reduce row sums over the 4 tig lanes
    lsum0 += __shfl_xor_sync(0xffffffffu, lsum0, 1);
    lsum0 += __shfl_xor_sync(0xffffffffu, lsum0, 2);
    lsum1 += __shfl_xor_sync(0xffffffffu, lsum1, 1);
    lsum1 += __shfl_xor_sync(0xffffffffu, lsum1, 2);
    float inv0 = 1.0f / lsum0, inv1 = 1.0f / lsum1;

    const int b = bh >> 4, h = bh & 15;
    float* y0 = yf + ((size_t)b * SEQ + q0 + r0 + g) * 1024 + h * 64;
    float* y1 = yf + ((size_t)b * SEQ + q0 + r0 + g + 8) * 1024 + h * 64;
    #pragma unroll
    for (int nt = 0; nt < 8; nt++) {
        int col = nt * 8 + 2 * tig;
        *(float2*)&y0[col] = make_float2(o[nt][0] * inv0, o[nt][1] * inv0);
        *(float2*)&y1[col] = make_float2(o[nt][2] * inv1, o[nt][3] * inv1);
    }
}

// ---------------------------------------------------------------------------
extern "C" void kernel_launch(void* const* d_in, const int* in_sizes, int n_in,
                              void* d_out, int out_size)
{
    const float* x      = (const float*)d_in[0];
    const float* w_kv_a = (const float*)d_in[1];
    const float* w_kv_b = (const float*)d_in[2];
    const float* w_q_a  = (const float*)d_in[3];
    const float* w_q_b  = (const float*)d_in[4];
    const float* w_proj = (const float*)d_in[5];
    const float* kv_nw  = (const float*)d_in[6];
    const float* q_nw   = (const float*)d_in[7];
    float* out = (float*)d_out;

    float *qlat, *kvlat, *y;
    __nv_bfloat16 *qh, *ql, *kh, *kl, *vh, *vl;
    cudaGetSymbolAddress((void**)&qlat,  g_qlat);
    cudaGetSymbolAddress((void**)&kvlat, g_kvlat);
    cudaGetSymbolAddress((void**)&y,     g_y);
    cudaGetSymbolAddress((void**)&qh, g_qh);  cudaGetSymbolAddress((void**)&ql, g_ql);
    cudaGetSymbolAddress((void**)&kh, g_kh);  cudaGetSymbolAddress((void**)&kl, g_kl);
    cudaGetSymbolAddress((void**)&vh, g_vh);  cudaGetSymbolAddress((void**)&vl, g_vl);

    cudaFuncSetAttribute(attn_tc,
                         cudaFuncAttributeMaxDynamicSharedMemorySize, ATTN_SMEM);

    // latent projections + fused rmsnorm
    gemm_lat<<<64, 256>>>(x, w_q_a,  q_nw,  qlat);
    gemm_lat<<<64, 256>>>(x, w_kv_a, kv_nw, kvlat);

    // up-projections -> bf16 hi/lo split, per-head layout
    gemm_up<0><<<dim3(8, 64),  256>>>(qlat,  w_q_b,  qh, ql, nullptr, nullptr, 64, 1024);
    gemm_up<1><<<dim3(16, 64), 256>>>(kvlat, w_kv_b, kh, kl, vh, vl, 64, 2048);

    // attention
    attn_tc<<<dim3(16, 64), 256, ATTN_SMEM>>>(qh, ql, kh, kl, vh, vl, y);

    // output projection
    gemm_tc<<<dim3(8, 64), 256>>>(y, w_proj, out, 1024, 1024);
}

// round 6
// speedup vs baseline: 3.0900x; 1.1430x over previous
#include <cuda_runtime.h>
#include <cuda_bf16.h>
#include <cstdint>

#define SEQ   2048
#define NTOK  8192

// ---------------- scratch (device globals: no runtime allocation) ----------
__device__ float g_qlat [(size_t)NTOK * 64];
__device__ float g_kvlat[(size_t)NTOK * 64];
__device__ float g_y  [(size_t)NTOK * 1024];
// bf16 hi/lo split tensors, per-head layout [(b*16+h)][seq][64]
__device__ __nv_bfloat16 g_qh[(size_t)NTOK * 1024];
__device__ __nv_bfloat16 g_ql[(size_t)NTOK * 1024];
__device__ __nv_bfloat16 g_kh[(size_t)NTOK * 1024];
__device__ __nv_bfloat16 g_kl[(size_t)NTOK * 1024];
__device__ __nv_bfloat16 g_vh[(size_t)NTOK * 1024];
__device__ __nv_bfloat16 g_vl[(size_t)NTOK * 1024];

// ---------------- helpers ---------------------------------------------------
static __device__ __forceinline__ uint32_t smem_u32(const void* p) {
    uint32_t a;
    asm("{ .reg .u64 t; cvta.to.shared.u64 t, %1; cvt.u32.u64 %0, t; }"
        : "=r"(a) : "l"(p));
    return a;
}
static __device__ __forceinline__ uint32_t bfpack(float lo, float hi) {
    uint32_t r;
    asm("cvt.rn.bf16x2.f32 %0, %1, %2;" : "=r"(r) : "f"(hi), "f"(lo));
    return r;
}
static __device__ __forceinline__ void split2(float x, float y,
                                              uint32_t& h, uint32_t& l) {
    h = bfpack(x, y);
    __nv_bfloat162 hb = *reinterpret_cast<__nv_bfloat162*>(&h);
    l = bfpack(x - __bfloat162float(hb.x), y - __bfloat162float(hb.y));
}
// swizzled smem addr: 128B rows of 8 x 16B chunks, chunk ^= row&7
static __device__ __forceinline__ uint32_t lda(uint32_t base, int row, int ch) {
    return base + row * 128 + (((uint32_t)ch ^ ((uint32_t)row & 7u)) << 4);
}

#define MMAB(c, a0, a1, a2, a3, b0, b1)                                        \
    asm volatile("mma.sync.aligned.m16n8k16.row.col.f32.bf16.bf16.f32 "        \
        "{%0,%1,%2,%3},{%4,%5,%6,%7},{%8,%9},{%0,%1,%2,%3};"                   \
        : "+f"((c)[0]), "+f"((c)[1]), "+f"((c)[2]), "+f"((c)[3])               \
        : "r"(a0), "r"(a1), "r"(a2), "r"(a3), "r"(b0), "r"(b1))

#define MMAX3(c, ah, al, bh0, bh1, bl0, bl1) do {                              \
    MMAB(c, (ah)[0], (ah)[1], (ah)[2], (ah)[3], bh0, bh1);                     \
    MMAB(c, (ah)[0], (ah)[1], (ah)[2], (ah)[3], bl0, bl1);                     \
    MMAB(c, (al)[0], (al)[1], (al)[2], (al)[3], bh0, bh1);                     \
} while (0)

#define LDSM4(r, addr)                                                         \
    asm volatile("ldmatrix.sync.aligned.m8n8.x4.shared.b16 {%0,%1,%2,%3}, [%4];" \
        : "=r"((r)[0]), "=r"((r)[1]), "=r"((r)[2]), "=r"((r)[3]) : "r"(addr))
#define LDSM4T(r, addr)                                                        \
    asm volatile("ldmatrix.sync.aligned.m8n8.x4.trans.shared.b16 {%0,%1,%2,%3}, [%4];" \
        : "=r"((r)[0]), "=r"((r)[1]), "=r"((r)[2]), "=r"((r)[3]) : "r"(addr))
#define CPA16(dst, src)                                                        \
    asm volatile("cp.async.cg.shared.global [%0], [%1], 16;" :: "r"(dst), "l"(src))
#define CPCOMMIT() asm volatile("cp.async.commit_group;" ::: "memory")
#define CPWAIT(n)  asm volatile("cp.async.wait_group %0;" :: "n"(n) : "memory")

// ======================================================================
// gemm_k<MODE>: C = A[M,K] @ B[N,K]^T, bf16x3, double-buffered smem +
// register prefetch. MODE 0: q-up (bf16 split out, scale 0.125)
// MODE 1: kv-up (k->H,L / v->H2,L2).  MODE 2: fp32 out (Cf).
// ======================================================================
template<int MODE>
__global__ __launch_bounds__(256, 2) void gemm_k(
    const float* __restrict__ A, const float* __restrict__ B,
    float* __restrict__ Cf,
    __nv_bfloat16* __restrict__ H,  __nv_bfloat16* __restrict__ L,
    __nv_bfloat16* __restrict__ H2, __nv_bfloat16* __restrict__ L2,
    int K, int N)
{
    __shared__ uint32_t AsW[2][128 * 20];
    __shared__ uint32_t BsW[2][128 * 20];
    const int tid = threadIdx.x;
    const int w = tid >> 5, lane = tid & 31;
    const int g = lane >> 2, tig = lane & 3;
    const int wm = w & 1, wn = w >> 1;
    const int m0 = blockIdx.y * 128, n0 = blockIdx.x * 128;
    const int CH = K >> 4;

    float c[4][4][4] = {};

    // stage chunk 0 into buf 0
    #pragma unroll
    for (int p = 0; p < 2; p++) {
        int f = tid + p * 256, r = f >> 2, c4 = f & 3;
        float4 va = *(const float4*)&A[(size_t)(m0 + r) * K + c4 * 4];
        uint32_t h0, h1, l0, l1;
        split2(va.x, va.y, h0, l0); split2(va.z, va.w, h1, l1);
        AsW[0][r*20+2*c4] = h0;     AsW[0][r*20+2*c4+1] = h1;
        AsW[0][r*20+8+2*c4] = l0;   AsW[0][r*20+9+2*c4] = l1;
        float4 vb = *(const float4*)&B[(size_t)(n0 + r) * K + c4 * 4];
        split2(vb.x, vb.y, h0, l0); split2(vb.z, vb.w, h1, l1);
        BsW[0][r*20+2*c4] = h0;     BsW[0][r*20+2*c4+1] = h1;
        BsW[0][r*20+8+2*c4] = l0;   BsW[0][r*20+9+2*c4] = l1;
    }
    __syncthreads();

    for (int cc = 0; cc < CH; cc++) {
        const int bi = cc & 1;
        const uint32_t* As = AsW[bi];
        const uint32_t* Bs = BsW[bi];
        uint32_t ah[4][4], al[4][4];
        #pragma unroll
        for (int mt = 0; mt < 4; mt++) {
            int r = wm * 64 + mt * 16 + g;
            ah[mt][0] = As[r*20+tig];      ah[mt][1] = As[(r+8)*20+tig];
            ah[mt][2] = As[r*20+4+tig];    ah[mt][3] = As[(r+8)*20+4+tig];
            al[mt][0] = As[r*20+8+tig];    al[mt][1] = As[(r+8)*20+8+tig];
            al[mt][2] = As[r*20+12+tig];   al[mt][3] = As[(r+8)*20+12+tig];
        }
        // issue global prefetch for next chunk (consumed after MMAs)
        float4 pa[2], pb[2];
        const bool pf = (cc + 1 < CH);
        if (pf) {
            #pragma unroll
            for (int p = 0; p < 2; p++) {
                int f = tid + p * 256, r = f >> 2, c4 = f & 3;
                pa[p] = *(const float4*)&A[(size_t)(m0+r)*K + (cc+1)*16 + c4*4];
                pb[p] = *(const float4*)&B[(size_t)(n0+r)*K + (cc+1)*16 + c4*4];
            }
        }
        #pragma unroll
        for (int nt = 0; nt < 4; nt++) {
            int rn = wn * 32 + nt * 8 + g;
            uint32_t bh0 = Bs[rn*20+tig],   bh1 = Bs[rn*20+4+tig];
            uint32_t bl0 = Bs[rn*20+8+tig], bl1 = Bs[rn*20+12+tig];
            #pragma unroll
            for (int mt = 0; mt < 4; mt++)
                MMAX3(c[mt][nt], ah[mt], al[mt], bh0, bh1, bl0, bl1);
        }
        if (pf) {
            #pragma unroll
            for (int p = 0; p < 2; p++) {
                int f = tid + p * 256, r = f >> 2, c4 = f & 3;
                uint32_t h0, h1, l0, l1;
                split2(pa[p].x, pa[p].y, h0, l0); split2(pa[p].z, pa[p].w, h1, l1);
                AsW[bi^1][r*20+2*c4] = h0;     AsW[bi^1][r*20+2*c4+1] = h1;
                AsW[bi^1][r*20+8+2*c4] = l0;   AsW[bi^1][r*20+9+2*c4] = l1;
                split2(pb[p].x, pb[p].y, h0, l0); split2(pb[p].z, pb[p].w, h1, l1);
                BsW[bi^1][r*20+2*c4] = h0;     BsW[bi^1][r*20+2*c4+1] = h1;
                BsW[bi^1][r*20+8+2*c4] = l0;   BsW[bi^1][r*20+9+2*c4] = l1;
            }
        }
        __syncthreads();
    }

    if (MODE == 2) {
        #pragma unroll
        for (int mt = 0; mt < 4; mt++)
            #pragma unroll
            for (int nt = 0; nt < 4; nt++) {
                int r0 = m0 + wm * 64 + mt * 16 + g;
                int col = n0 + wn * 32 + nt * 8 + 2 * tig;
                *(float2*)&Cf[(size_t)r0 * N + col]       = make_float2(c[mt][nt][0], c[mt][nt][1]);
                *(float2*)&Cf[(size_t)(r0 + 8) * N + col] = make_float2(c[mt][nt][2], c[mt][nt][3]);
            }
    } else {
        const float sc = (MODE == 0) ? 0.125f : 1.0f;
        #pragma unroll
        for (int mt = 0; mt < 4; mt++)
            #pragma unroll
            for (int nt = 0; nt < 4; nt++) {
                int tok = m0 + wm * 64 + mt * 16 + g;
                int col = n0 + wn * 32 + nt * 8 + 2 * tig;
                int b = tok >> 11, tn = tok & 2047;
                int h, d;
                __nv_bfloat16 *DH, *DL;
                if (MODE == 0) {
                    h = col >> 6; d = col & 63; DH = H; DL = L;
                } else {
                    h = col >> 7; int rr = col & 127; d = rr & 63;
                    if (rr < 64) { DH = H; DL = L; } else { DH = H2; DL = L2; }
                }
                size_t a0 = (((size_t)b * 16 + h) * SEQ + tn) * 64 + d;
                size_t a1 = a0 + 8 * 64;
                uint32_t hp, lp;
                split2(c[mt][nt][0] * sc, c[mt][nt][1] * sc, hp, lp);
                *(uint32_t*)&DH[a0] = hp;  *(uint32_t*)&DL[a0] = lp;
                split2(c[mt][nt][2] * sc, c[mt][nt][3] * sc, hp, lp);
                *(uint32_t*)&DH[a1] = hp;  *(uint32_t*)&DL[a1] = lp;
            }
    }
}

// ======================================================================
// gemm_lat2: BOTH latent projections in one launch (blockIdx.y selects).
// C[8192,64] = rmsnorm(A @ W^T) * nw, double-buffered, shfl rmsnorm.
// ======================================================================
__global__ __launch_bounds__(256, 2) void gemm_lat2(
    const float* __restrict__ A,
    const float* __restrict__ Wq, const float* __restrict__ Wkv,
    const float* __restrict__ nwq, const float* __restrict__ nwkv,
    float* __restrict__ Cq, float* __restrict__ Ckv)
{
    __shared__ uint32_t AsW[2][128 * 20];
    __shared__ uint32_t BsW[2][64 * 20];
    __shared__ float ssm[2][128];
    __shared__ float nws[64];
    const float* W  = blockIdx.y ? Wkv  : Wq;
    const float* nw = blockIdx.y ? nwkv : nwq;
    float* C        = blockIdx.y ? Ckv  : Cq;

    const int tid = threadIdx.x;
    const int w = tid >> 5, lane = tid & 31;
    const int g = lane >> 2, tig = lane & 3;
    const int wm = w >> 1, wn = w & 1;
    const int m0 = blockIdx.x * 128;

    if (tid < 64) nws[tid] = nw[tid];

    float c[2][4][4] = {};

    // stage chunk 0
    #pragma unroll
    for (int p = 0; p < 2; p++) {
        int f = tid + p * 256, r = f >> 2, c4 = f & 3;
        float4 va = *(const float4*)&A[(size_t)(m0 + r) * 1024 + c4 * 4];
        uint32_t h0, h1, l0, l1;
        split2(va.x, va.y, h0, l0); split2(va.z, va.w, h1, l1);
        AsW[0][r*20+2*c4] = h0;     AsW[0][r*20+2*c4+1] = h1;
        AsW[0][r*20+8+2*c4] = l0;   AsW[0][r*20+9+2*c4] = l1;
    }
    {
        int r = tid >> 2, c4 = tid & 3;
        float4 vb = *(const float4*)&W[(size_t)r * 1024 + c4 * 4];
        uint32_t h0, h1, l0, l1;
        split2(vb.x, vb.y, h0, l0); split2(vb.z, vb.w, h1, l1);
        BsW[0][r*20+2*c4] = h0;     BsW[0][r*20+2*c4+1] = h1;
        BsW[0][r*20+8+2*c4] = l0;   BsW[0][r*20+9+2*c4] = l1;
    }
    __syncthreads();

    for (int cc = 0; cc < 64; cc++) {
        const int bi = cc & 1;
        const uint32_t* As = AsW[bi];
        const uint32_t* Bs = BsW[bi];
        uint32_t ah[2][4], al[2][4];
        #pragma unroll
        for (int mt = 0; mt < 2; mt++) {
            int r = wm * 32 + mt * 16 + g;
            ah[mt][0] = As[r*20+tig];      ah[mt][1] = As[(r+8)*20+tig];
            ah[mt][2] = As[r*20+4+tig];    ah[mt][3] = As[(r+8)*20+4+tig];
            al[mt][0] = As[r*20+8+tig];    al[mt][1] = As[(r+8)*20+8+tig];
            al[mt][2] = As[r*20+12+tig];   al[mt][3] = As[(r+8)*20+12+tig];
        }
        float4 pa[2], pbv;
        const bool pf = (cc + 1 < 64);
        if (pf) {
            #pragma unroll
            for (int p = 0; p < 2; p++) {
                int f = tid + p * 256, r = f >> 2, c4 = f & 3;
                pa[p] = *(const float4*)&A[(size_t)(m0+r)*1024 + (cc+1)*16 + c4*4];
            }
            int r = tid >> 2, c4 = tid & 3;
            pbv = *(const float4*)&W[(size_t)r * 1024 + (cc+1)*16 + c4*4];
        }
        #pragma unroll
        for (int nt = 0; nt < 4; nt++) {
            int rn = wn * 32 + nt * 8 + g;
            uint32_t bh0 = Bs[rn*20+tig],   bh1 = Bs[rn*20+4+tig];
            uint32_t bl0 = Bs[rn*20+8+tig], bl1 = Bs[rn*20+12+tig];
            #pragma unroll
            for (int mt = 0; mt < 2; mt++)
                MMAX3(c[mt][nt], ah[mt], al[mt], bh0, bh1, bl0, bl1);
        }
        if (pf) {
            #pragma unroll
            for (int p = 0; p < 2; p++) {
                int f = tid + p * 256, r = f >> 2, c4 = f & 3;
                uint32_t h0, h1, l0, l1;
                split2(pa[p].x, pa[p].y, h0, l0); split2(pa[p].z, pa[p].w, h1, l1);
                AsW[bi^1][r*20+2*c4] = h0;     AsW[bi^1][r*20+2*c4+1] = h1;
                AsW[bi^1][r*20+8+2*c4] = l0;   AsW[bi^1][r*20+9+2*c4] = l1;
            }
            int r = tid >> 2, c4 = tid & 3;
            uint32_t h0, h1, l0, l1;
            split2(pbv.x, pbv.y, h0, l0); split2(pbv.z, pbv.w, h1, l1);
            BsW[bi^1][r*20+2*c4] = h0;     BsW[bi^1][r*20+2*c4+1] = h1;
            BsW[bi^1][r*20+8+2*c4] = l0;   BsW[bi^1][r*20+9+2*c4] = l1;
        }
        __syncthreads();
    }

    // rmsnorm: per-row sum of squares via shfl (tig) + cross-warp smem
    #pragma unroll
    for (int mt = 0; mt < 2; mt++) {
        int r = wm * 32 + mt * 16 + g;
        float p0 = 0.f, p1 = 0.f;
        #pragma unroll
        for (int nt = 0; nt < 4; nt++) {
            p0 += c[mt][nt][0]*c[mt][nt][0] + c[mt][nt][1]*c[mt][nt][1];
            p1 += c[mt][nt][2]*c[mt][nt][2] + c[mt][nt][3]*c[mt][nt][3];
        }
        p0 += __shfl_xor_sync(0xffffffffu, p0, 1);
        p0 += __shfl_xor_sync(0xffffffffu, p0, 2);
        p1 += __shfl_xor_sync(0xffffffffu, p1, 1);
        p1 += __shfl_xor_sync(0xffffffffu, p1, 2);
        if (tig == 0) { ssm[wn][r] = p0; ssm[wn][r + 8] = p1; }
    }
    __syncthreads();
    #pragma unroll
    for (int mt = 0; mt < 2; mt++) {
        int r = wm * 32 + mt * 16 + g;
        float s0 = rsqrtf((ssm[0][r]     + ssm[1][r])     * (1.0f/64.0f) + 1e-6f);
        float s1 = rsqrtf((ssm[0][r + 8] + ssm[1][r + 8]) * (1.0f/64.0f) + 1e-6f);
        #pragma unroll
        for (int nt = 0; nt < 4; nt++) {
            int col = wn * 32 + nt * 8 + 2 * tig;
            *(float2*)&C[(size_t)(m0 + r) * 64 + col] =
                make_float2(c[mt][nt][0]*s0*nws[col], c[mt][nt][1]*s0*nws[col+1]);
            *(float2*)&C[(size_t)(m0 + r + 8) * 64 + col] =
                make_float2(c[mt][nt][2]*s1*nws[col], c[mt][nt][3]*s1*nws[col+1]);
        }
    }
}

// ======================================================================
// attn_tc: flash attention, bf16x3 mma.sync, ldmatrix fragments.
// 64-key sub-chunks, DOUBLE-buffered cp.async within 96KB -> 2 CTAs/SM.
// ======================================================================
#define ATTN_SMEM 98304

__global__ __launch_bounds__(256, 2) void attn_tc(
    const __nv_bfloat16* __restrict__ qh_g, const __nv_bfloat16* __restrict__ ql_g,
    const __nv_bfloat16* __restrict__ kh_g, const __nv_bfloat16* __restrict__ kl_g,
    const __nv_bfloat16* __restrict__ vh_g, const __nv_bfloat16* __restrict__ vl_g,
    float* __restrict__ yf)
{
    extern __shared__ char smraw[];
    const uint32_t base = smem_u32(smraw);
    const uint32_t Qh = base, Ql = base + 16384;
    const uint32_t kvb = base + 32768;
    // buf bi: Kh = kvb + bi*32768, Kl = +8192, Vh = +16384, Vl = +24576

    const int tid = threadIdx.x;
    const int w = tid >> 5, lane = tid & 31;
    const int g = lane >> 2, tig = lane & 3;
    const int l8 = lane & 7, sub = lane >> 3;
    const int r0 = w * 16;
    const int bh = blockIdx.y;
    const int q0 = blockIdx.x * 128;
    const size_t hb = (size_t)bh * SEQ;

    // ---- group 0: Q + sub-chunk 0 ; group 1: sub-chunk 1 ----
    #pragma unroll
    for (int p = 0; p < 4; p++) {
        int idx = tid + p * 256, row = idx >> 3, ch = idx & 7;
        size_t go = (hb + q0 + row) * 64 + ch * 8;
        CPA16(lda(Qh, row, ch), qh_g + go);
        CPA16(lda(Ql, row, ch), ql_g + go);
    }
    #pragma unroll
    for (int p = 0; p < 2; p++) {
        int idx = tid + p * 256, row = idx >> 3, ch = idx & 7;
        size_t go = (hb + row) * 64 + ch * 8;
        uint32_t so = (uint32_t)row * 128 + (((uint32_t)ch ^ ((uint32_t)row & 7u)) << 4);
        CPA16(kvb + so,         kh_g + go);  CPA16(kvb + 8192 + so,  kl_g + go);
        CPA16(kvb + 16384 + so, vh_g + go);  CPA16(kvb + 24576 + so, vl_g + go);
    }
    CPCOMMIT();
    #pragma unroll
    for (int p = 0; p < 2; p++) {
        int idx = tid + p * 256, row = idx >> 3, ch = idx & 7;
        size_t go = (hb + 64 + row) * 64 + ch * 8;
        uint32_t so = (uint32_t)row * 128 + (((uint32_t)ch ^ ((uint32_t)row & 7u)) << 4);
        CPA16(kvb + 32768 + so, kh_g + go);  CPA16(kvb + 40960 + so, kl_g + go);
        CPA16(kvb + 49152 + so, vh_g + go);  CPA16(kvb + 57344 + so, vl_g + go);
    }
    CPCOMMIT();

    float o[8][4] = {};
    float lsum0 = 0.f, lsum1 = 0.f;

    for (int sc = 0; sc < 32; sc++) {
        const int bi = sc & 1;
        const uint32_t Kh = kvb + bi * 32768,      Kl = Kh + 8192;
        const uint32_t Vh = Kh + 16384,            Vl = Kh + 24576;
        CPWAIT(1);
        __syncthreads();

        // ---- S = Q @ K^T over 64 keys ----
        float s[8][4] = {};
        #pragma unroll
        for (int ks = 0; ks < 4; ks++) {
            int arow = r0 + l8 + ((sub & 1) << 3);
            int ach  = 2 * ks + (sub >> 1);
            uint32_t ah[4], al[4];
            LDSM4(ah, lda(Qh, arow, ach));
            LDSM4(al, lda(Ql, arow, ach));
            #pragma unroll
            for (int ntp = 0; ntp < 4; ntp++) {
                int krow = ntp * 16 + ((sub >> 1) << 3) + l8;
                int kch  = 2 * ks + (sub & 1);
                uint32_t bhf[4], blf[4];
                LDSM4(bhf, lda(Kh, krow, kch));
                LDSM4(blf, lda(Kl, krow, kch));
                MMAX3(s[2 * ntp],     ah, al, bhf[0], bhf[1], blf[0], blf[1]);
                MMAX3(s[2 * ntp + 1], ah, al, bhf[2], bhf[3], blf[2], blf[3]);
            }
        }

        // ---- exp + PV per 16-key group ----
        #pragma unroll
        for (int ks = 0; ks < 4; ks++) {
            float e0 = __expf(s[2*ks][0]),   e1 = __expf(s[2*ks][1]);
            float e2 = __expf(s[2*ks][2]),   e3 = __expf(s[2*ks][3]);
            float e4 = __expf(s[2*ks+1][0]), e5 = __expf(s[2*ks+1][1]);
            float e6 = __expf(s[2*ks+1][2]), e7 = __expf(s[2*ks+1][3]);
            lsum0 += e0 + e1 + e4 + e5;
            lsum1 += e2 + e3 + e6 + e7;
            uint32_t ph[4], pl[4];
            split2(e0, e1, ph[0], pl[0]);
            split2(e2, e3, ph[1], pl[1]);
            split2(e4, e5, ph[2], pl[2]);
            split2(e6, e7, ph[3], pl[3]);
            #pragma unroll
            for (int ntp = 0; ntp < 4; ntp++) {
                int vrow = ks * 16 + ((sub & 1) << 3) + l8;
                int vch  = 2 * ntp + (sub >> 1);
                uint32_t vhf[4], vlf[4];
                LDSM4T(vhf, lda(Vh, vrow, vch));
                LDSM4T(vlf, lda(Vl, vrow, vch));
                MMAX3(o[2 * ntp],     ph, pl, vhf[0], vhf[1], vlf[0], vlf[1]);
                MMAX3(o[2 * ntp + 1], ph, pl, vhf[2], vhf[3], vlf[2], vlf[3]);
            }
        }

        __syncthreads();   // all warps done with buf bi before restage
        if (sc + 2 < 32) {
            #pragma unroll
            for (int p = 0; p < 2; p++) {
                int idx = tid + p * 256, row = idx >> 3, ch = idx & 7;
                size_t go = (hb + (size_t)(sc + 2) * 64 + row) * 64 + ch * 8;
                uint32_t so = (uint32_t)row * 128 + (((uint32_t)ch ^ ((uint32_t)row & 7u)) << 4);
                CPA16(Kh + so, kh_g + go);  CPA16(Kl + so, kl_g + go);
                CPA16(Vh + so, vh_g + go);  CPA16(Vl + so, vl_g + go);
            }
        }
        CPCOMMIT();
    }

    // reduce row sums over the 4 tig lanes
    lsum0 += __shfl_xor_sync(0xffffffffu, lsum0, 1);
    lsum0 += __shfl_xor_sync(0xffffffffu, lsum0, 2);
    lsum1 += __shfl_xor_sync(0xffffffffu, lsum1, 1);
    lsum1 += __shfl_xor_sync(0xffffffffu, lsum1, 2);
    float inv0 = 1.0f / lsum0, inv1 = 1.0f / lsum1;

    const int b = bh >> 4, h = bh & 15;
    float* y0 = yf + ((size_t)b * SEQ + q0 + r0 + g) * 1024 + h * 64;
    float* y1 = yf + ((size_t)b * SEQ + q0 + r0 + g + 8) * 1024 + h * 64;
    #pragma unroll
    for (int nt = 0; nt < 8; nt++) {
        int col = nt * 8 + 2 * tig;
        *(float2*)&y0[col] = make_float2(o[nt][0] * inv0, o[nt][1] * inv0);
        *(float2*)&y1[col] = make_float2(o[nt][2] * inv1, o[nt][3] * inv1);
    }
}

// ---------------------------------------------------------------------------
extern "C" void kernel_launch(void* const* d_in, const int* in_sizes, int n_in,
                              void* d_out, int out_size)
{
    const float* x      = (const float*)d_in[0];
    const float* w_kv_a = (const float*)d_in[1];
    const float* w_kv_b = (const float*)d_in[2];
    const float* w_q_a  = (const float*)d_in[3];
    const float* w_q_b  = (const float*)d_in[4];
    const float* w_proj = (const float*)d_in[5];
    const float* kv_nw  = (const float*)d_in[6];
    const float* q_nw   = (const float*)d_in[7];
    float* out = (float*)d_out;

    float *qlat, *kvlat, *y;
    __nv_bfloat16 *qh, *ql, *kh, *kl, *vh, *vl;
    cudaGetSymbolAddress((void**)&qlat,  g_qlat);
    cudaGetSymbolAddress((void**)&kvlat, g_kvlat);
    cudaGetSymbolAddress((void**)&y,     g_y);
    cudaGetSymbolAddress((void**)&qh, g_qh);  cudaGetSymbolAddress((void**)&ql, g_ql);
    cudaGetSymbolAddress((void**)&kh, g_kh);  cudaGetSymbolAddress((void**)&kl, g_kl);
    cudaGetSymbolAddress((void**)&vh, g_vh);  cudaGetSymbolAddress((void**)&vl, g_vl);

    cudaFuncSetAttribute(attn_tc,
                         cudaFuncAttributeMaxDynamicSharedMemorySize, ATTN_SMEM);

    // latent projections + fused rmsnorm (both in one launch)
    gemm_lat2<<<dim3(64, 2), 256>>>(x, w_q_a, w_kv_a, q_nw, kv_nw, qlat, kvlat);

    // up-projections -> bf16 hi/lo split, per-head layout
    gemm_k<0><<<dim3(8, 64),  256>>>(qlat,  w_q_b,  nullptr, qh, ql, nullptr, nullptr, 64, 1024);
    gemm_k<1><<<dim3(16, 64), 256>>>(kvlat, w_kv_b, nullptr, kh, kl, vh, vl, 64, 2048);

    // attention
    attn_tc<<<dim3(16, 64), 256, ATTN_SMEM>>>(qh, ql, kh, kl, vh, vl, y);

    // output projection
    gemm_k<2><<<dim3(8, 64), 256>>>(y, w_proj, out, nullptr, nullptr, nullptr, nullptr, 1024, 1024);
}

// round 7
// speedup vs baseline: 3.3175x; 1.0736x over previous
#include <cuda_runtime.h>
#include <cuda_bf16.h>
#include <cstdint>

#define SEQ   2048
#define NTOK  8192

// ---------------- scratch (device globals: no runtime allocation) ----------
// interleaved split layout: [row][k/32][32 hi bf16 | 32 lo bf16]  (128B rows)
__device__ __nv_bfloat16 g_qlat_s [(size_t)NTOK * 128];
__device__ __nv_bfloat16 g_kvlat_s[(size_t)NTOK * 128];
__device__ __nv_bfloat16 g_wq_s   [(size_t)1024 * 128];
__device__ __nv_bfloat16 g_wkv_s  [(size_t)2048 * 128];
__device__ __nv_bfloat16 g_wproj_s[(size_t)1024 * 2048];
__device__ __nv_bfloat16 g_ys     [(size_t)NTOK * 2048];
// per-head split tensors for attention [(b*16+h)][seq][64]
__device__ __nv_bfloat16 g_qh[(size_t)NTOK * 1024];
__device__ __nv_bfloat16 g_ql[(size_t)NTOK * 1024];
__device__ __nv_bfloat16 g_kh[(size_t)NTOK * 1024];
__device__ __nv_bfloat16 g_kl[(size_t)NTOK * 1024];
__device__ __nv_bfloat16 g_vh[(size_t)NTOK * 1024];
__device__ __nv_bfloat16 g_vl[(size_t)NTOK * 1024];

#define QSCALE (0.125f * 1.4426950408889634f)   // fold softmax scale * log2e

// ---------------- helpers ---------------------------------------------------
static __device__ __forceinline__ uint32_t smem_u32(const void* p) {
    uint32_t a;
    asm("{ .reg .u64 t; cvta.to.shared.u64 t, %1; cvt.u32.u64 %0, t; }"
        : "=r"(a) : "l"(p));
    return a;
}
static __device__ __forceinline__ uint32_t bfpack(float lo, float hi) {
    uint32_t r;
    asm("cvt.rn.bf16x2.f32 %0, %1, %2;" : "=r"(r) : "f"(hi), "f"(lo));
    return r;
}
static __device__ __forceinline__ void split2(float x, float y,
                                              uint32_t& h, uint32_t& l) {
    h = bfpack(x, y);
    __nv_bfloat162 hb = *reinterpret_cast<__nv_bfloat162*>(&h);
    l = bfpack(x - __bfloat162float(hb.x), y - __bfloat162float(hb.y));
}
static __device__ __forceinline__ float ex2f(float x) {
    float y; asm("ex2.approx.f32 %0, %1;" : "=f"(y) : "f"(x)); return y;
}
// swizzled smem addr: 128B rows of 8 x 16B chunks, chunk ^= row&7
static __device__ __forceinline__ uint32_t lda(uint32_t base, int row, int ch) {
    return base + row * 128 + (((uint32_t)ch ^ ((uint32_t)row & 7u)) << 4);
}

#define MMAB(c, a0, a1, a2, a3, b0, b1)                                        \
    asm volatile("mma.sync.aligned.m16n8k16.row.col.f32.bf16.bf16.f32 "        \
        "{%0,%1,%2,%3},{%4,%5,%6,%7},{%8,%9},{%0,%1,%2,%3};"                   \
        : "+f"((c)[0]), "+f"((c)[1]), "+f"((c)[2]), "+f"((c)[3])               \
        : "r"(a0), "r"(a1), "r"(a2), "r"(a3), "r"(b0), "r"(b1))

#define MMAX3(c, ah, al, bh0, bh1, bl0, bl1) do {                              \
    MMAB(c, (ah)[0], (ah)[1], (ah)[2], (ah)[3], bh0, bh1);                     \
    MMAB(c, (ah)[0], (ah)[1], (ah)[2], (ah)[3], bl0, bl1);                     \
    MMAB(c, (al)[0], (al)[1], (al)[2], (al)[3], bh0, bh1);                     \
} while (0)

#define LDSM4(r, addr)                                                         \
    asm volatile("ldmatrix.sync.aligned.m8n8.x4.shared.b16 {%0,%1,%2,%3}, [%4];" \
        : "=r"((r)[0]), "=r"((r)[1]), "=r"((r)[2]), "=r"((r)[3]) : "r"(addr))
#define LDSM4T(r, addr)                                                        \
    asm volatile("ldmatrix.sync.aligned.m8n8.x4.trans.shared.b16 {%0,%1,%2,%3}, [%4];" \
        : "=r"((r)[0]), "=r"((r)[1]), "=r"((r)[2]), "=r"((r)[3]) : "r"(addr))
#define CPA16(dst, src)                                                        \
    asm volatile("cp.async.cg.shared.global [%0], [%1], 16;" :: "r"(dst), "l"(src))
#define CPCOMMIT() asm volatile("cp.async.commit_group;" ::: "memory")
#define CPWAIT(n)  asm volatile("cp.async.wait_group %0;" :: "n"(n) : "memory")

// ======================================================================
// wsplit: W[n][K] fp32 -> O[n][K/32][32h|32l] bf16
// ======================================================================
__global__ __launch_bounds__(256) void wsplit(
    const float* __restrict__ W, __nv_bfloat16* __restrict__ O,
    int K, int nf4)
{
    int idx = blockIdx.x * 256 + threadIdx.x;
    if (idx >= nf4) return;
    int K4 = K >> 2;
    int n = idx / K4, k4 = idx - n * K4;
    float4 v = *(const float4*)&W[(size_t)n * K + k4 * 4];
    int k = k4 * 4, kc = k >> 5, p = k & 31;
    size_t o = ((size_t)n * (K >> 5) + kc) * 64 + p;
    uint32_t h0, l0, h1, l1;
    split2(v.x, v.y, h0, l0); split2(v.z, v.w, h1, l1);
    *(uint32_t*)&O[o]      = h0;  *(uint32_t*)&O[o + 2]  = h1;
    *(uint32_t*)&O[o + 32] = l0;  *(uint32_t*)&O[o + 34] = l1;
}

// ======================================================================
// gemm_bf<MODE>: C = A[M,K] @ B[N,K]^T, both pre-split interleaved bf16.
// BK=32, cp.async double-buffered, ldmatrix, x3 MMA. 2 CTAs/SM.
// MODE 0: q-up (scale QSCALE -> qh/ql per-head)
// MODE 1: kv-up (k->H,L / v->H2,L2)      MODE 2: fp32 out (Cf)
// ======================================================================
#define GEMMBF_SMEM 65536

template<int MODE>
__global__ __launch_bounds__(256, 2) void gemm_bf(
    const __nv_bfloat16* __restrict__ A, const __nv_bfloat16* __restrict__ B,
    float* __restrict__ Cf,
    __nv_bfloat16* __restrict__ H,  __nv_bfloat16* __restrict__ L,
    __nv_bfloat16* __restrict__ H2, __nv_bfloat16* __restrict__ L2,
    int K, int N)
{
    extern __shared__ char smraw[];
    const uint32_t base = smem_u32(smraw);
    // buf s: A at base + s*32768, B at +16384

    const int tid = threadIdx.x;
    const int w = tid >> 5, lane = tid & 31;
    const int g = lane >> 2, tig = lane & 3;
    const int l8 = lane & 7, sub = lane >> 3;
    const int wm = w & 1, wn = w >> 1;
    const int m0 = blockIdx.y * 128, n0 = blockIdx.x * 128;
    const int KC = K >> 5, CH = KC;

    float c[4][4][4] = {};

    // stage chunks 0,1
    #pragma unroll
    for (int s = 0; s < 2; s++) {
        if (s < CH) {
            #pragma unroll
            for (int p = 0; p < 4; p++) {
                int idx = tid + p * 256, row = idx >> 3, ch = idx & 7;
                CPA16(lda(base + s * 32768, row, ch),
                      A + ((size_t)(m0 + row) * KC + s) * 64 + ch * 8);
                CPA16(lda(base + s * 32768 + 16384, row, ch),
                      B + ((size_t)(n0 + row) * KC + s) * 64 + ch * 8);
            }
        }
        CPCOMMIT();
    }

    for (int cc = 0; cc < CH; cc++) {
        const uint32_t Ab = base + (cc & 1) * 32768;
        const uint32_t Bb = Ab + 16384;
        CPWAIT(1);
        __syncthreads();

        #pragma unroll
        for (int ks = 0; ks < 2; ks++) {
            uint32_t ah[4][4], al[4][4];
            #pragma unroll
            for (int mt = 0; mt < 4; mt++) {
                int arow = wm * 64 + mt * 16 + l8 + ((sub & 1) << 3);
                int hch  = 2 * ks + (sub >> 1);
                LDSM4(ah[mt], lda(Ab, arow, hch));
                LDSM4(al[mt], lda(Ab, arow, hch + 4));
            }
            #pragma unroll
            for (int np = 0; np < 2; np++) {
                int brow = wn * 32 + np * 16 + ((sub >> 1) << 3) + l8;
                int bch  = 2 * ks + (sub & 1);
                uint32_t bhf[4], blf[4];
                LDSM4(bhf, lda(Bb, brow, bch));
                LDSM4(blf, lda(Bb, brow, bch + 4));
                #pragma unroll
                for (int mt = 0; mt < 4; mt++) {
                    MMAX3(c[mt][2*np],   ah[mt], al[mt], bhf[0], bhf[1], blf[0], blf[1]);
                    MMAX3(c[mt][2*np+1], ah[mt], al[mt], bhf[2], bhf[3], blf[2], blf[3]);
                }
            }
        }

        __syncthreads();
        if (cc + 2 < CH) {
            #pragma unroll
            for (int p = 0; p < 4; p++) {
                int idx = tid + p * 256, row = idx >> 3, ch = idx & 7;
                CPA16(lda(Ab, row, ch),
                      A + ((size_t)(m0 + row) * KC + cc + 2) * 64 + ch * 8);
                CPA16(lda(Bb, row, ch),
                      B + ((size_t)(n0 + row) * KC + cc + 2) * 64 + ch * 8);
            }
        }
        CPCOMMIT();
    }

    if (MODE == 2) {
        #pragma unroll
        for (int mt = 0; mt < 4; mt++)
            #pragma unroll
            for (int nt = 0; nt < 4; nt++) {
                int r0 = m0 + wm * 64 + mt * 16 + g;
                int col = n0 + wn * 32 + nt * 8 + 2 * tig;
                *(float2*)&Cf[(size_t)r0 * N + col]       = make_float2(c[mt][nt][0], c[mt][nt][1]);
                *(float2*)&Cf[(size_t)(r0 + 8) * N + col] = make_float2(c[mt][nt][2], c[mt][nt][3]);
            }
    } else {
        const float sc = (MODE == 0) ? QSCALE : 1.0f;
        #pragma unroll
        for (int mt = 0; mt < 4; mt++)
            #pragma unroll
            for (int nt = 0; nt < 4; nt++) {
                int tok = m0 + wm * 64 + mt * 16 + g;
                int col = n0 + wn * 32 + nt * 8 + 2 * tig;
                int b = tok >> 11, tn = tok & 2047;
                int h, d;
                __nv_bfloat16 *DH, *DL;
                if (MODE == 0) {
                    h = col >> 6; d = col & 63; DH = H; DL = L;
                } else {
                    h = col >> 7; int rr = col & 127; d = rr & 63;
                    if (rr < 64) { DH = H; DL = L; } else { DH = H2; DL = L2; }
                }
                size_t a0 = (((size_t)b * 16 + h) * SEQ + tn) * 64 + d;
                size_t a1 = a0 + 8 * 64;
                uint32_t hp, lp;
                split2(c[mt][nt][0] * sc, c[mt][nt][1] * sc, hp, lp);
                *(uint32_t*)&DH[a0] = hp;  *(uint32_t*)&DL[a0] = lp;
                split2(c[mt][nt][2] * sc, c[mt][nt][3] * sc, hp, lp);
                *(uint32_t*)&DH[a1] = hp;  *(uint32_t*)&DL[a1] = lp;
            }
    }
}

// ======================================================================
// gemm_lat2: BOTH latent projections in one launch (blockIdx.y selects).
// out = rmsnorm(A @ W^T) * nw, written split-interleaved [tok][2][64]
// ======================================================================
__global__ __launch_bounds__(256, 2) void gemm_lat2(
    const float* __restrict__ A,
    const float* __restrict__ Wq, const float* __restrict__ Wkv,
    const float* __restrict__ nwq, const float* __restrict__ nwkv,
    __nv_bfloat16* __restrict__ Cq, __nv_bfloat16* __restrict__ Ckv)
{
    __shared__ uint32_t AsW[2][128 * 20];
    __shared__ uint32_t BsW[2][64 * 20];
    __shared__ float ssm[2][128];
    __shared__ float nws[64];
    const float* W  = blockIdx.y ? Wkv  : Wq;
    const float* nw = blockIdx.y ? nwkv : nwq;
    __nv_bfloat16* C = blockIdx.y ? Ckv : Cq;

    const int tid = threadIdx.x;
    const int w = tid >> 5, lane = tid & 31;
    const int g = lane >> 2, tig = lane & 3;
    const int wm = w >> 1, wn = w & 1;
    const int m0 = blockIdx.x * 128;

    if (tid < 64) nws[tid] = nw[tid];

    float c[2][4][4] = {};

    #pragma unroll
    for (int p = 0; p < 2; p++) {
        int f = tid + p * 256, r = f >> 2, c4 = f & 3;
        float4 va = *(const float4*)&A[(size_t)(m0 + r) * 1024 + c4 * 4];
        uint32_t h0, h1, l0, l1;
        split2(va.x, va.y, h0, l0); split2(va.z, va.w, h1, l1);
        AsW[0][r*20+2*c4] = h0;     AsW[0][r*20+2*c4+1] = h1;
        AsW[0][r*20+8+2*c4] = l0;   AsW[0][r*20+9+2*c4] = l1;
    }
    {
        int r = tid >> 2, c4 = tid & 3;
        float4 vb = *(const float4*)&W[(size_t)r * 1024 + c4 * 4];
        uint32_t h0, h1, l0, l1;
        split2(vb.x, vb.y, h0, l0); split2(vb.z, vb.w, h1, l1);
        BsW[0][r*20+2*c4] = h0;     BsW[0][r*20+2*c4+1] = h1;
        BsW[0][r*20+8+2*c4] = l0;   BsW[0][r*20+9+2*c4] = l1;
    }
    __syncthreads();

    for (int cc = 0; cc < 64; cc++) {
        const int bi = cc & 1;
        const uint32_t* As = AsW[bi];
        const uint32_t* Bs = BsW[bi];
        uint32_t ah[2][4], al[2][4];
        #pragma unroll
        for (int mt = 0; mt < 2; mt++) {
            int r = wm * 32 + mt * 16 + g;
            ah[mt][0] = As[r*20+tig];      ah[mt][1] = As[(r+8)*20+tig];
            ah[mt][2] = As[r*20+4+tig];    ah[mt][3] = As[(r+8)*20+4+tig];
            al[mt][0] = As[r*20+8+tig];    al[mt][1] = As[(r+8)*20+8+tig];
            al[mt][2] = As[r*20+12+tig];   al[mt][3] = As[(r+8)*20+12+tig];
        }
        float4 pa[2], pbv;
        const bool pf = (cc + 1 < 64);
        if (pf) {
            #pragma unroll
            for (int p = 0; p < 2; p++) {
                int f = tid + p * 256, r = f >> 2, c4 = f & 3;
                pa[p] = *(const float4*)&A[(size_t)(m0+r)*1024 + (cc+1)*16 + c4*4];
            }
            int r = tid >> 2, c4 = tid & 3;
            pbv = *(const float4*)&W[(size_t)r * 1024 + (cc+1)*16 + c4*4];
        }
        #pragma unroll
        for (int nt = 0; nt < 4; nt++) {
            int rn = wn * 32 + nt * 8 + g;
            uint32_t bh0 = Bs[rn*20+tig],   bh1 = Bs[rn*20+4+tig];
            uint32_t bl0 = Bs[rn*20+8+tig], bl1 = Bs[rn*20+12+tig];
            #pragma unroll
            for (int mt = 0; mt < 2; mt++)
                MMAX3(c[mt][nt], ah[mt], al[mt], bh0, bh1, bl0, bl1);
        }
        if (pf) {
            #pragma unroll
            for (int p = 0; p < 2; p++) {
                int f = tid + p * 256, r = f >> 2, c4 = f & 3;
                uint32_t h0, h1, l0, l1;
                split2(pa[p].x, pa[p].y, h0, l0); split2(pa[p].z, pa[p].w, h1, l1);
                AsW[bi^1][r*20+2*c4] = h0;     AsW[bi^1][r*20+2*c4+1] = h1;
                AsW[bi^1][r*20+8+2*c4] = l0;   AsW[bi^1][r*20+9+2*c4] = l1;
            }
            int r = tid >> 2, c4 = tid & 3;
            uint32_t h0, h1, l0, l1;
            split2(pbv.x, pbv.y, h0, l0); split2(pbv.z, pbv.w, h1, l1);
            BsW[bi^1][r*20+2*c4] = h0;     BsW[bi^1][r*20+2*c4+1] = h1;
            BsW[bi^1][r*20+8+2*c4] = l0;   BsW[bi^1][r*20+9+2*c4] = l1;
        }
        __syncthreads();
    }

    // rmsnorm: per-row sum of squares via shfl + cross-warp smem
    #pragma unroll
    for (int mt = 0; mt < 2; mt++) {
        int r = wm * 32 + mt * 16 + g;
        float p0 = 0.f, p1 = 0.f;
        #pragma unroll
        for (int nt = 0; nt < 4; nt++) {
            p0 += c[mt][nt][0]*c[mt][nt][0] + c[mt][nt][1]*c[mt][nt][1];
            p1 += c[mt][nt][2]*c[mt][nt][2] + c[mt][nt][3]*c[mt][nt][3];
        }
        p0 += __shfl_xor_sync(0xffffffffu, p0, 1);
        p0 += __shfl_xor_sync(0xffffffffu, p0, 2);
        p1 += __shfl_xor_sync(0xffffffffu, p1, 1);
        p1 += __shfl_xor_sync(0xffffffffu, p1, 2);
        if (tig == 0) { ssm[wn][r] = p0; ssm[wn][r + 8] = p1; }
    }
    __syncthreads();
    #pragma unroll
    for (int mt = 0; mt < 2; mt++) {
        int r = wm * 32 + mt * 16 + g;
        float s0 = rsqrtf((ssm[0][r]     + ssm[1][r])     * (1.0f/64.0f) + 1e-6f);
        float s1 = rsqrtf((ssm[0][r + 8] + ssm[1][r + 8]) * (1.0f/64.0f) + 1e-6f);
        #pragma unroll
        for (int nt = 0; nt < 4; nt++) {
            int col = wn * 32 + nt * 8 + 2 * tig;
            int kc = col >> 5, p = col & 31;
            uint32_t hh, ll;
            size_t b0 = ((size_t)(m0 + r) * 2 + kc) * 64 + p;
            split2(c[mt][nt][0]*s0*nws[col], c[mt][nt][1]*s0*nws[col+1], hh, ll);
            *(uint32_t*)&C[b0] = hh;  *(uint32_t*)&C[b0 + 32] = ll;
            size_t b1 = ((size_t)(m0 + r + 8) * 2 + kc) * 64 + p;
            split2(c[mt][nt][2]*s1*nws[col], c[mt][nt][3]*s1*nws[col+1], hh, ll);
            *(uint32_t*)&C[b1] = hh;  *(uint32_t*)&C[b1 + 32] = ll;
        }
    }
}

// ======================================================================
// attn_tc: flash attention, bf16x3 mma.sync, ldmatrix fragments.
// 64-key sub-chunks double-buffered. Q pre-scaled by 0.125*log2e -> ex2.
// Output written split-interleaved into ys [tok][32][64].
// ======================================================================
#define ATTN_SMEM 98304

__global__ __launch_bounds__(256, 2) void attn_tc(
    const __nv_bfloat16* __restrict__ qh_g, const __nv_bfloat16* __restrict__ ql_g,
    const __nv_bfloat16* __restrict__ kh_g, const __nv_bfloat16* __restrict__ kl_g,
    const __nv_bfloat16* __restrict__ vh_g, const __nv_bfloat16* __restrict__ vl_g,
    __nv_bfloat16* __restrict__ ys)
{
    extern __shared__ char smraw[];
    const uint32_t base = smem_u32(smraw);
    const uint32_t Qh = base, Ql = base + 16384;
    const uint32_t kvb = base + 32768;

    const int tid = threadIdx.x;
    const int w = tid >> 5, lane = tid & 31;
    const int g = lane >> 2, tig = lane & 3;
    const int l8 = lane & 7, sub = lane >> 3;
    const int r0 = w * 16;
    const int bh = blockIdx.y;
    const int q0 = blockIdx.x * 128;
    const size_t hb = (size_t)bh * SEQ;

    #pragma unroll
    for (int p = 0; p < 4; p++) {
        int idx = tid + p * 256, row = idx >> 3, ch = idx & 7;
        size_t go = (hb + q0 + row) * 64 + ch * 8;
        CPA16(lda(Qh, row, ch), qh_g + go);
        CPA16(lda(Ql, row, ch), ql_g + go);
    }
    #pragma unroll
    for (int p = 0; p < 2; p++) {
        int idx = tid + p * 256, row = idx >> 3, ch = idx & 7;
        size_t go = (hb + row) * 64 + ch * 8;
        uint32_t so = (uint32_t)row * 128 + (((uint32_t)ch ^ ((uint32_t)row & 7u)) << 4);
        CPA16(kvb + so,         kh_g + go);  CPA16(kvb + 8192 + so,  kl_g + go);
        CPA16(kvb + 16384 + so, vh_g + go);  CPA16(kvb + 24576 + so, vl_g + go);
    }
    CPCOMMIT();
    #pragma unroll
    for (int p = 0; p < 2; p++) {
        int idx = tid + p * 256, row = idx >> 3, ch = idx & 7;
        size_t go = (hb + 64 + row) * 64 + ch * 8;
        uint32_t so = (uint32_t)row * 128 + (((uint32_t)ch ^ ((uint32_t)row & 7u)) << 4);
        CPA16(kvb + 32768 + so, kh_g + go);  CPA16(kvb + 40960 + so, kl_g + go);
        CPA16(kvb + 49152 + so, vh_g + go);  CPA16(kvb + 57344 + so, vl_g + go);
    }
    CPCOMMIT();

    float o[8][4] = {};
    float lsum0 = 0.f, lsum1 = 0.f;

    for (int sc = 0; sc < 32; sc++) {
        const int bi = sc & 1;
        const uint32_t Kh = kvb + bi * 32768, Kl = Kh + 8192;
        const uint32_t Vh = Kh + 16384,       Vl = Kh + 24576;
        CPWAIT(1);
        __syncthreads();

        float s[8][4] = {};
        #pragma unroll
        for (int ks = 0; ks < 4; ks++) {
            int arow = r0 + l8 + ((sub & 1) << 3);
            int ach  = 2 * ks + (sub >> 1);
            uint32_t ah[4], al[4];
            LDSM4(ah, lda(Qh, arow, ach));
            LDSM4(al, lda(Ql, arow, ach));
            #pragma unroll
            for (int ntp = 0; ntp < 4; ntp++) {
                int krow = ntp * 16 + ((sub >> 1) << 3) + l8;
                int kch  = 2 * ks + (sub & 1);
                uint32_t bhf[4], blf[4];
                LDSM4(bhf, lda(Kh, krow, kch));
                LDSM4(blf, lda(Kl, krow, kch));
                MMAX3(s[2 * ntp],     ah, al, bhf[0], bhf[1], blf[0], blf[1]);
                MMAX3(s[2 * ntp + 1], ah, al, bhf[2], bhf[3], blf[2], blf[3]);
            }
        }

        #pragma unroll
        for (int ks = 0; ks < 4; ks++) {
            float e0 = ex2f(s[2*ks][0]),   e1 = ex2f(s[2*ks][1]);
            float e2 = ex2f(s[2*ks][2]),   e3 = ex2f(s[2*ks][3]);
            float e4 = ex2f(s[2*ks+1][0]), e5 = ex2f(s[2*ks+1][1]);
            float e6 = ex2f(s[2*ks+1][2]), e7 = ex2f(s[2*ks+1][3]);
            lsum0 += e0 + e1 + e4 + e5;
            lsum1 += e2 + e3 + e6 + e7;
            uint32_t ph[4], pl[4];
            split2(e0, e1, ph[0], pl[0]);
            split2(e2, e3, ph[1], pl[1]);
            split2(e4, e5, ph[2], pl[2]);
            split2(e6, e7, ph[3], pl[3]);
            #pragma unroll
            for (int ntp = 0; ntp < 4; ntp++) {
                int vrow = ks * 16 + ((sub & 1) << 3) + l8;
                int vch  = 2 * ntp + (sub >> 1);
                uint32_t vhf[4], vlf[4];
                LDSM4T(vhf, lda(Vh, vrow, vch));
                LDSM4T(vlf, lda(Vl, vrow, vch));
                MMAX3(o[2 * ntp],     ph, pl, vhf[0], vhf[1], vlf[0], vlf[1]);
                MMAX3(o[2 * ntp + 1], ph, pl, vhf[2], vhf[3], vlf[2], vlf[3]);
            }
        }

        __syncthreads();
        if (sc + 2 < 32) {
            #pragma unroll
            for (int p = 0; p < 2; p++) {
                int idx = tid + p * 256, row = idx >> 3, ch = idx & 7;
                size_t go = (hb + (size_t)(sc + 2) * 64 + row) * 64 + ch * 8;
                uint32_t so = (uint32_t)row * 128 + (((uint32_t)ch ^ ((uint32_t)row & 7u)) << 4);
                CPA16(Kh + so, kh_g + go);  CPA16(Kl + so, kl_g + go);
                CPA16(Vh + so, vh_g + go);  CPA16(Vl + so, vl_g + go);
            }
        }
        CPCOMMIT();
    }

    lsum0 += __shfl_xor_sync(0xffffffffu, lsum0, 1);
    lsum0 += __shfl_xor_sync(0xffffffffu, lsum0, 2);
    lsum1 += __shfl_xor_sync(0xffffffffu, lsum1, 1);
    lsum1 += __shfl_xor_sync(0xffffffffu, lsum1, 2);
    float inv0 = 1.0f / lsum0, inv1 = 1.0f / lsum1;

    const int b = bh >> 4, h = bh & 15;
    const size_t tok0 = (size_t)b * SEQ + q0 + r0 + g;
    #pragma unroll
    for (int nt = 0; nt < 8; nt++) {
        int col = nt * 8 + 2 * tig;
        int kc = 2 * h + (col >> 5), p = col & 31;
        uint32_t hh, ll;
        size_t b0 = (tok0 * 32 + kc) * 64 + p;
        split2(o[nt][0] * inv0, o[nt][1] * inv0, hh, ll);
        *(uint32_t*)&ys[b0] = hh;  *(uint32_t*)&ys[b0 + 32] = ll;
        size_t b1 = ((tok0 + 8) * 32 + kc) * 64 + p;
        split2(o[nt][2] * inv1, o[nt][3] * inv1, hh, ll);
        *(uint32_t*)&ys[b1] = hh;  *(uint32_t*)&ys[b1 + 32] = ll;
    }
}

// ---------------------------------------------------------------------------
extern "C" void kernel_launch(void* const* d_in, const int* in_sizes, int n_in,
                              void* d_out, int out_size)
{
    const float* x      = (const float*)d_in[0];
    const float* w_kv_a = (const float*)d_in[1];
    const float* w_kv_b = (const float*)d_in[2];
    const float* w_q_a  = (const float*)d_in[3];
    const float* w_q_b  = (const float*)d_in[4];
    const float* w_proj = (const float*)d_in[5];
    const float* kv_nw  = (const float*)d_in[6];
    const float* q_nw   = (const float*)d_in[7];
    float* out = (float*)d_out;

    __nv_bfloat16 *qlat_s, *kvlat_s, *wq_s, *wkv_s, *wproj_s, *ysv;
    __nv_bfloat16 *qh, *ql, *kh, *kl, *vh, *vl;
    cudaGetSymbolAddress((void**)&qlat_s,  g_qlat_s);
    cudaGetSymbolAddress((void**)&kvlat_s, g_kvlat_s);
    cudaGetSymbolAddress((void**)&wq_s,    g_wq_s);
    cudaGetSymbolAddress((void**)&wkv_s,   g_wkv_s);
    cudaGetSymbolAddress((void**)&wproj_s, g_wproj_s);
    cudaGetSymbolAddress((void**)&ysv,     g_ys);
    cudaGetSymbolAddress((void**)&qh, g_qh);  cudaGetSymbolAddress((void**)&ql, g_ql);
    cudaGetSymbolAddress((void**)&kh, g_kh);  cudaGetSymbolAddress((void**)&kl, g_kl);
    cudaGetSymbolAddress((void**)&vh, g_vh);  cudaGetSymbolAddress((void**)&vl, g_vl);

    cudaFuncSetAttribute(attn_tc,    cudaFuncAttributeMaxDynamicSharedMemorySize, ATTN_SMEM);
    cudaFuncSetAttribute(gemm_bf<0>, cudaFuncAttributeMaxDynamicSharedMemorySize, GEMMBF_SMEM);
    cudaFuncSetAttribute(gemm_bf<1>, cudaFuncAttributeMaxDynamicSharedMemorySize, GEMMBF_SMEM);
    cudaFuncSetAttribute(gemm_bf<2>, cudaFuncAttributeMaxDynamicSharedMemorySize, GEMMBF_SMEM);

    // pre-split weights into interleaved bf16 layout
    wsplit<<<64,   256>>>(w_q_b,  wq_s,    64,   16384);
    wsplit<<<128,  256>>>(w_kv_b, wkv_s,   64,   32768);
    wsplit<<<1024, 256>>>(w_proj, wproj_s, 1024, 262144);

    // latent projections + fused rmsnorm -> split-interleaved latents
    gemm_lat2<<<dim3(64, 2), 256>>>(x, w_q_a, w_kv_a, q_nw, kv_nw, qlat_s, kvlat_s);

    // up-projections -> per-head split tensors
    gemm_bf<0><<<dim3(8, 64),  256, GEMMBF_SMEM>>>(qlat_s,  wq_s,  nullptr, qh, ql, nullptr, nullptr, 64, 1024);
    gemm_bf<1><<<dim3(16, 64), 256, GEMMBF_SMEM>>>(kvlat_s, wkv_s, nullptr, kh, kl, vh, vl, 64, 2048);

    // attention -> split-interleaved y
    attn_tc<<<dim3(16, 64), 256, ATTN_SMEM>>>(qh, ql, kh, kl, vh, vl, ysv);

    // output projection (fp32 out)
    gemm_bf<2><<<dim3(8, 64), 256, GEMMBF_SMEM>>>(ysv, wproj_s, out, nullptr, nullptr, nullptr, nullptr, 1024, 1024);
}